// round 1
// baseline (speedup 1.0000x reference)
#include <cuda_runtime.h>
#include <cstdint>
#include <cstddef>

// Problem constants
#define BB   4
#define SS   2048
#define DD   1024
#define HH   16
#define HD   64
#define NTOK (BB*SS)          // 8192
#define D3   (3*DD)           // 3072
#define D4   (4*DD)           // 4096

// ---------------- scratch (device globals: allocation-guard safe) -------------
__device__ float g_h  [NTOK*DD];   // LN1 output
__device__ float g_qkv[NTOK*D3];   // qkv
__device__ float g_att[NTOK*DD];   // attention output (merged heads)
__device__ float g_x2 [NTOK*DD];   // residual 1 output
__device__ float g_m  [NTOK*DD];   // LN2 output
__device__ float g_fc [NTOK*D4];   // gelu(fc) output

// ---------------- layernorm ---------------------------------------------------
__global__ void ln_kernel(const float* __restrict__ x, const float* __restrict__ w,
                          const float* __restrict__ b, float* __restrict__ out)
{
    int row = blockIdx.x;
    int tid = threadIdx.x;
    const float4* xr = reinterpret_cast<const float4*>(x + (size_t)row * DD);
    float4 v = xr[tid];
    float s  = v.x + v.y + v.z + v.w;
    float ss = v.x*v.x + v.y*v.y + v.z*v.z + v.w*v.w;

    __shared__ float red0[8], red1[8], stat[2];
    #pragma unroll
    for (int o = 16; o; o >>= 1) {
        s  += __shfl_xor_sync(0xffffffffu, s,  o);
        ss += __shfl_xor_sync(0xffffffffu, ss, o);
    }
    int wid = tid >> 5, lane = tid & 31;
    if (lane == 0) { red0[wid] = s; red1[wid] = ss; }
    __syncthreads();
    if (tid == 0) {
        float ts = 0.f, tss = 0.f;
        #pragma unroll
        for (int i = 0; i < 8; i++) { ts += red0[i]; tss += red1[i]; }
        float mean = ts * (1.0f / DD);
        float var  = tss * (1.0f / DD) - mean * mean;
        stat[0] = mean;
        stat[1] = rsqrtf(var + 1e-5f);
    }
    __syncthreads();
    float mean = stat[0], rstd = stat[1];

    const float4* wv4 = reinterpret_cast<const float4*>(w);
    const float4* bv4 = reinterpret_cast<const float4*>(b);
    float4 wv = wv4[tid], bv = bv4[tid];
    float4 o;
    o.x = wv.x * (v.x - mean) * rstd + bv.x;
    o.y = wv.y * (v.y - mean) * rstd + bv.y;
    o.z = wv.z * (v.z - mean) * rstd + bv.z;
    o.w = wv.w * (v.w - mean) * rstd + bv.w;
    reinterpret_cast<float4*>(out + (size_t)row * DD)[tid] = o;
}

// ---------------- GEMM: C[M,N] = A[M,K] @ B[K,N] + bias (+res / gelu) ----------
#define EPI_NONE 0
#define EPI_RES  1
#define EPI_GELU 2

__device__ __forceinline__ float gelu_f(float v)
{
    float c = 0.7978845608028654f * (v + 0.044715f * v * v * v);
    return 0.5f * v * (1.0f + tanhf(c));
}

// BM=BN=128, BK=16, 256 threads, 8x8 micro-tile split 4+4 (conflict-free LDS.128)
__global__ void gemm_kernel(const float* __restrict__ A, const float* __restrict__ B,
                            const float* __restrict__ bias, const float* __restrict__ res,
                            float* __restrict__ C, int M, int N, int K, int epi)
{
    __shared__ float As[16][128];
    __shared__ float Bs[16][128];

    const int bx = blockIdx.x;   // N tile
    const int by = blockIdx.y;   // M tile
    const int tid = threadIdx.x;
    const int tx = tid & 15;     // 0..15 (N dir)
    const int ty = tid >> 4;     // 0..15 (M dir)

    float acc[8][8];
    #pragma unroll
    for (int i = 0; i < 8; i++)
        #pragma unroll
        for (int j = 0; j < 8; j++) acc[i][j] = 0.f;

    const float* Ab = A + (size_t)by * 128 * K;
    const float* Bb = B + (size_t)bx * 128;

    const int arow = tid >> 2;          // 0..63 (x2)
    const int acol = (tid & 3) * 4;     // 0,4,8,12
    const int brow = tid >> 5;          // 0..7 (x2)
    const int bcol = (tid & 31) * 4;    // 0..124

    for (int k0 = 0; k0 < K; k0 += 16) {
        #pragma unroll
        for (int i = 0; i < 2; i++) {
            int r = arow + i * 64;
            float4 v = *reinterpret_cast<const float4*>(Ab + (size_t)r * K + k0 + acol);
            As[acol + 0][r] = v.x; As[acol + 1][r] = v.y;
            As[acol + 2][r] = v.z; As[acol + 3][r] = v.w;
        }
        #pragma unroll
        for (int i = 0; i < 2; i++) {
            int r = brow + i * 8;
            float4 v = *reinterpret_cast<const float4*>(Bb + (size_t)(k0 + r) * N + bcol);
            *reinterpret_cast<float4*>(&Bs[r][bcol]) = v;
        }
        __syncthreads();

        #pragma unroll
        for (int kk = 0; kk < 16; kk++) {
            float4 a0 = *reinterpret_cast<const float4*>(&As[kk][ty * 4]);
            float4 a1 = *reinterpret_cast<const float4*>(&As[kk][64 + ty * 4]);
            float4 b0 = *reinterpret_cast<const float4*>(&Bs[kk][tx * 4]);
            float4 b1 = *reinterpret_cast<const float4*>(&Bs[kk][64 + tx * 4]);
            float ra[8] = {a0.x, a0.y, a0.z, a0.w, a1.x, a1.y, a1.z, a1.w};
            float rb[8] = {b0.x, b0.y, b0.z, b0.w, b1.x, b1.y, b1.z, b1.w};
            #pragma unroll
            for (int i = 0; i < 8; i++)
                #pragma unroll
                for (int j = 0; j < 8; j++)
                    acc[i][j] += ra[i] * rb[j];
        }
        __syncthreads();
    }

    // epilogue
    #pragma unroll
    for (int ih = 0; ih < 2; ih++) {
        #pragma unroll
        for (int ii = 0; ii < 4; ii++) {
            int r = by * 128 + ih * 64 + ty * 4 + ii;
            #pragma unroll
            for (int jh = 0; jh < 2; jh++) {
                int c0 = bx * 128 + jh * 64 + tx * 4;
                float4 v;
                v.x = acc[ih * 4 + ii][jh * 4 + 0] + bias[c0 + 0];
                v.y = acc[ih * 4 + ii][jh * 4 + 1] + bias[c0 + 1];
                v.z = acc[ih * 4 + ii][jh * 4 + 2] + bias[c0 + 2];
                v.w = acc[ih * 4 + ii][jh * 4 + 3] + bias[c0 + 3];
                if (epi == EPI_RES) {
                    float4 rv = *reinterpret_cast<const float4*>(res + (size_t)r * N + c0);
                    v.x += rv.x; v.y += rv.y; v.z += rv.z; v.w += rv.w;
                } else if (epi == EPI_GELU) {
                    v.x = gelu_f(v.x); v.y = gelu_f(v.y);
                    v.z = gelu_f(v.z); v.w = gelu_f(v.w);
                }
                *reinterpret_cast<float4*>(C + (size_t)r * N + c0) = v;
            }
        }
    }
}

// ---------------- flash attention (causal, fp32) ------------------------------
// grid: (S/64, B*H), 256 threads. Thread (tq = tid/4, c = tid%4) owns:
//   scores j = 4*j16 + c (j16 = 0..15), output dims d = 4*dd + c (dd = 0..15)
#define ATT_STRIDE 65
#define ATT_SMEM   (4 * 64 * ATT_STRIDE * 4)  // Q,K,V,P tiles: 66560 B

__global__ void attn_kernel(const float* __restrict__ qkv, float* __restrict__ out)
{
    extern __shared__ float sm[];
    float* Qs = sm;
    float* Ks = Qs + 64 * ATT_STRIDE;
    float* Vs = Ks + 64 * ATT_STRIDE;
    float* Ps = Vs + 64 * ATT_STRIDE;

    const int qt  = blockIdx.x;           // query tile (0..31)
    const int bh  = blockIdx.y;           // 0..63
    const int bb  = bh >> 4;
    const int hh  = bh & 15;
    const int tid = threadIdx.x;
    const int tq  = tid >> 2;             // 0..63
    const int c   = tid & 3;              // 0..3

    // load + pre-scale Q tile (scale = 1/sqrt(64) = 0.125)
    #pragma unroll
    for (int l = 0; l < 16; l++) {
        int idx = l * 256 + tid;
        int r = idx >> 6, col = idx & 63;
        size_t g = ((size_t)(bb * SS + qt * 64 + r)) * D3 + hh * HD + col;
        Qs[r * ATT_STRIDE + col] = qkv[g] * 0.125f;
    }

    float O[16];
    #pragma unroll
    for (int i = 0; i < 16; i++) O[i] = 0.f;
    float mrun = -1e30f, lrun = 0.f;

    for (int kt = 0; kt <= qt; kt++) {
        // load K, V tiles
        #pragma unroll
        for (int l = 0; l < 16; l++) {
            int idx = l * 256 + tid;
            int r = idx >> 6, col = idx & 63;
            size_t g = ((size_t)(bb * SS + kt * 64 + r)) * D3 + DD + hh * HD + col;
            Ks[r * ATT_STRIDE + col] = qkv[g];
            Vs[r * ATT_STRIDE + col] = qkv[g + DD];
        }
        __syncthreads();

        // scores: s[j16] = Q[tq] . K[4*j16+c]
        float s[16];
        #pragma unroll
        for (int j16 = 0; j16 < 16; j16++) s[j16] = 0.f;
        #pragma unroll 8
        for (int d = 0; d < 64; d++) {
            float qd = Qs[tq * ATT_STRIDE + d];
            #pragma unroll
            for (int j16 = 0; j16 < 16; j16++)
                s[j16] += qd * Ks[(4 * j16 + c) * ATT_STRIDE + d];
        }
        if (kt == qt) {
            #pragma unroll
            for (int j16 = 0; j16 < 16; j16++)
                if (4 * j16 + c > tq) s[j16] = -1e30f;
        }

        // row max across 16 local + the 4-lane group
        float tmax = s[0];
        #pragma unroll
        for (int j16 = 1; j16 < 16; j16++) tmax = fmaxf(tmax, s[j16]);
        tmax = fmaxf(tmax, __shfl_xor_sync(0xffffffffu, tmax, 1));
        tmax = fmaxf(tmax, __shfl_xor_sync(0xffffffffu, tmax, 2));

        float newm = fmaxf(mrun, tmax);
        float corr = __expf(mrun - newm);

        float psum = 0.f;
        #pragma unroll
        for (int j16 = 0; j16 < 16; j16++) {
            float p = __expf(s[j16] - newm);
            s[j16] = p;
            psum += p;
        }
        psum += __shfl_xor_sync(0xffffffffu, psum, 1);
        psum += __shfl_xor_sync(0xffffffffu, psum, 2);
        lrun = lrun * corr + psum;
        mrun = newm;

        #pragma unroll
        for (int dd = 0; dd < 16; dd++) O[dd] *= corr;

        #pragma unroll
        for (int j16 = 0; j16 < 16; j16++)
            Ps[tq * ATT_STRIDE + 4 * j16 + c] = s[j16];
        __syncthreads();

        // O[tq][4*dd+c] += sum_j P[tq][j] * V[j][4*dd+c]
        #pragma unroll 8
        for (int j = 0; j < 64; j++) {
            float p = Ps[tq * ATT_STRIDE + j];
            #pragma unroll
            for (int dd = 0; dd < 16; dd++)
                O[dd] += p * Vs[j * ATT_STRIDE + 4 * dd + c];
        }
        __syncthreads();
    }

    float inv = 1.0f / lrun;
    size_t gq = (size_t)(bb * SS + qt * 64 + tq);
    #pragma unroll
    for (int dd = 0; dd < 16; dd++)
        out[gq * DD + hh * HD + 4 * dd + c] = O[dd] * inv;
}

// ---------------- launcher -----------------------------------------------------
extern "C" void kernel_launch(void* const* d_in, const int* in_sizes, int n_in,
                              void* d_out, int out_size)
{
    const float* x       = (const float*)d_in[0];
    const float* ln1_w   = (const float*)d_in[1];
    const float* ln1_b   = (const float*)d_in[2];
    const float* W_attn  = (const float*)d_in[3];
    const float* b_attn  = (const float*)d_in[4];
    const float* W_cproj = (const float*)d_in[5];
    const float* b_cproj = (const float*)d_in[6];
    const float* ln2_w   = (const float*)d_in[7];
    const float* ln2_b   = (const float*)d_in[8];
    const float* W_fc    = (const float*)d_in[9];
    const float* b_fc    = (const float*)d_in[10];
    const float* W_mproj = (const float*)d_in[11];
    const float* b_mproj = (const float*)d_in[12];
    float* out = (float*)d_out;

    float *h, *qkv, *att, *x2, *m, *fc;
    cudaGetSymbolAddress((void**)&h,   g_h);
    cudaGetSymbolAddress((void**)&qkv, g_qkv);
    cudaGetSymbolAddress((void**)&att, g_att);
    cudaGetSymbolAddress((void**)&x2,  g_x2);
    cudaGetSymbolAddress((void**)&m,   g_m);
    cudaGetSymbolAddress((void**)&fc,  g_fc);

    cudaFuncSetAttribute(attn_kernel, cudaFuncAttributeMaxDynamicSharedMemorySize, ATT_SMEM);

    // 1. LN1
    ln_kernel<<<NTOK, 256>>>(x, ln1_w, ln1_b, h);

    // 2. qkv = h @ W_attn + b_attn
    {
        dim3 g(D3 / 128, NTOK / 128);
        gemm_kernel<<<g, 256>>>(h, W_attn, b_attn, nullptr, qkv, NTOK, D3, DD, EPI_NONE);
    }

    // 3. attention
    {
        dim3 g(SS / 64, BB * HH);
        attn_kernel<<<g, 256, ATT_SMEM>>>(qkv, att);
    }

    // 4. x2 = att @ W_cproj + b_cproj + x
    {
        dim3 g(DD / 128, NTOK / 128);
        gemm_kernel<<<g, 256>>>(att, W_cproj, b_cproj, x, x2, NTOK, DD, DD, EPI_RES);
    }

    // 5. LN2
    ln_kernel<<<NTOK, 256>>>(x2, ln2_w, ln2_b, m);

    // 6. fc = gelu(m @ W_fc + b_fc)
    {
        dim3 g(D4 / 128, NTOK / 128);
        gemm_kernel<<<g, 256>>>(m, W_fc, b_fc, nullptr, fc, NTOK, D4, DD, EPI_GELU);
    }

    // 7. out = fc @ W_mproj + b_mproj + x2
    {
        dim3 g(DD / 128, NTOK / 128);
        gemm_kernel<<<g, 256>>>(fc, W_mproj, b_mproj, x2, out, NTOK, DD, D4, EPI_RES);
    }
}

// round 3
// speedup vs baseline: 2.0084x; 2.0084x over previous
#include <cuda_runtime.h>
#include <cuda_bf16.h>
#include <cstdint>
#include <cstddef>

typedef __nv_bfloat16 bf16;

// Problem constants
#define BB   4
#define SS   2048
#define DD   1024
#define HH   16
#define HD   64
#define NTOK (BB*SS)          // 8192
#define D3   (3*DD)           // 3072
#define D4   (4*DD)           // 4096

// ---------------- scratch (device globals) ------------------------------------
__device__ float g_qkv[NTOK*D3];
__device__ float g_x2 [NTOK*DD];
__device__ bf16  g_h_hi [NTOK*DD],  g_h_lo [NTOK*DD];
__device__ bf16  g_att_hi[NTOK*DD], g_att_lo[NTOK*DD];
__device__ bf16  g_m_hi [NTOK*DD],  g_m_lo [NTOK*DD];
__device__ bf16  g_fc_hi[NTOK*D4],  g_fc_lo[NTOK*D4];

// transposed weights (hi/lo): Wt[N][K]
#define WATTN_OFF  0
#define WCPROJ_OFF (DD*D3)
#define WFC_OFF    (WCPROJ_OFF + DD*DD)
#define WMPROJ_OFF (WFC_OFF + DD*D4)
#define WTOTAL     (WMPROJ_OFF + D4*DD)
__device__ bf16 g_wt_hi[WTOTAL], g_wt_lo[WTOTAL];

// ---------------- helpers ------------------------------------------------------
__device__ __forceinline__ uint32_t smem_u32(const void* p) {
    uint32_t a;
    asm("{ .reg .u64 t; cvta.to.shared.u64 t, %1; cvt.u32.u64 %0, t; }" : "=r"(a) : "l"(p));
    return a;
}

__device__ __forceinline__ uint32_t sw128(uint32_t b) { return b ^ ((b >> 3) & 0x70); }

__device__ __forceinline__ void cp16(uint32_t saddr, const void* gaddr) {
    asm volatile("cp.async.cg.shared.global [%0], [%1], 16;" :: "r"(saddr), "l"(gaddr));
}
#define CP_COMMIT() asm volatile("cp.async.commit_group;" ::: "memory")
#define CP_WAIT(n)  asm volatile("cp.async.wait_group %0;" :: "n"(n) : "memory")

#define LDSM_X4(r, addr) \
    asm volatile("ldmatrix.sync.aligned.m8n8.x4.shared.b16 {%0,%1,%2,%3}, [%4];" \
        : "=r"((r)[0]), "=r"((r)[1]), "=r"((r)[2]), "=r"((r)[3]) : "r"(addr))

__device__ __forceinline__ void mma16816(float* c, const uint32_t* a,
                                         uint32_t b0, uint32_t b1)
{
    asm volatile(
        "mma.sync.aligned.m16n8k16.row.col.f32.bf16.bf16.f32 "
        "{%0,%1,%2,%3}, {%4,%5,%6,%7}, {%8,%9}, {%0,%1,%2,%3};"
        : "+f"(c[0]), "+f"(c[1]), "+f"(c[2]), "+f"(c[3])
        : "r"(a[0]), "r"(a[1]), "r"(a[2]), "r"(a[3]), "r"(b0), "r"(b1));
}

__device__ __forceinline__ void split2(float v, bf16& hi, bf16& lo)
{
    hi = __float2bfloat16(v);
    lo = __float2bfloat16(v - __bfloat162float(hi));
}

__device__ __forceinline__ float gelu_f(float v)
{
    float c = 0.7978845608028654f * (v + 0.044715f * v * v * v);
    return 0.5f * v * (1.0f + tanhf(c));
}

// ---------------- weight transpose + split:  W[K][N] -> Wt_hi/lo[N][K] --------
__global__ void wconv_kernel(const float* __restrict__ W, bf16* __restrict__ hi,
                             bf16* __restrict__ lo, int K, int N)
{
    __shared__ float t[32][33];
    int n0 = blockIdx.x * 32, k0 = blockIdx.y * 32;
    int tx = threadIdx.x, ty = threadIdx.y;   // 32 x 8
    #pragma unroll
    for (int i = 0; i < 4; i++)
        t[ty + i * 8][tx] = W[(size_t)(k0 + ty + i * 8) * N + n0 + tx];
    __syncthreads();
    #pragma unroll
    for (int i = 0; i < 4; i++) {
        float v = t[tx][ty + i * 8];
        size_t o = (size_t)(n0 + ty + i * 8) * K + k0 + tx;
        bf16 h, l; split2(v, h, l);
        hi[o] = h; lo[o] = l;
    }
}

// ---------------- layernorm -> bf16 hi/lo --------------------------------------
__global__ void ln_kernel(const float* __restrict__ x, const float* __restrict__ w,
                          const float* __restrict__ b, bf16* __restrict__ hi,
                          bf16* __restrict__ lo)
{
    int row = blockIdx.x;
    int tid = threadIdx.x;
    const float4* xr = reinterpret_cast<const float4*>(x + (size_t)row * DD);
    float4 v = xr[tid];
    float s  = v.x + v.y + v.z + v.w;
    float ss = v.x*v.x + v.y*v.y + v.z*v.z + v.w*v.w;

    __shared__ float red0[8], red1[8], stat[2];
    #pragma unroll
    for (int o = 16; o; o >>= 1) {
        s  += __shfl_xor_sync(0xffffffffu, s,  o);
        ss += __shfl_xor_sync(0xffffffffu, ss, o);
    }
    int wid = tid >> 5, lane = tid & 31;
    if (lane == 0) { red0[wid] = s; red1[wid] = ss; }
    __syncthreads();
    if (tid == 0) {
        float ts = 0.f, tss = 0.f;
        #pragma unroll
        for (int i = 0; i < 8; i++) { ts += red0[i]; tss += red1[i]; }
        float mean = ts * (1.0f / DD);
        float var  = tss * (1.0f / DD) - mean * mean;
        stat[0] = mean;
        stat[1] = rsqrtf(var + 1e-5f);
    }
    __syncthreads();
    float mean = stat[0], rstd = stat[1];

    float4 wv = reinterpret_cast<const float4*>(w)[tid];
    float4 bv = reinterpret_cast<const float4*>(b)[tid];
    float o0 = wv.x * (v.x - mean) * rstd + bv.x;
    float o1 = wv.y * (v.y - mean) * rstd + bv.y;
    float o2 = wv.z * (v.z - mean) * rstd + bv.z;
    float o3 = wv.w * (v.w - mean) * rstd + bv.w;
    bf16 h0,l0,h1,l1,h2,l2,h3,l3;
    split2(o0,h0,l0); split2(o1,h1,l1); split2(o2,h2,l2); split2(o3,h3,l3);
    __nv_bfloat162* Hh = reinterpret_cast<__nv_bfloat162*>(hi + (size_t)row * DD);
    __nv_bfloat162* Hl = reinterpret_cast<__nv_bfloat162*>(lo + (size_t)row * DD);
    __nv_bfloat162 p;
    p.x = h0; p.y = h1; Hh[tid*2]   = p;
    p.x = h2; p.y = h3; Hh[tid*2+1] = p;
    p.x = l0; p.y = l1; Hl[tid*2]   = p;
    p.x = l2; p.y = l3; Hl[tid*2+1] = p;
}

// ---------------- HMMA bf16x3 GEMM ---------------------------------------------
// C[M,N] = A[M,K] @ Bt[N,K]^T, A/Bt as bf16 hi/lo. BM=BN=128, BK=64.
// 256 threads = 8 warps, warp tile 32(m) x 64(n).
// epi: 0 = bias -> f32 ; 1 = bias + res -> f32 ; 2 = gelu(bias) -> bf16 hi/lo
#define SM_AHI 0
#define SM_ALO 16384
#define SM_BHI 32768
#define SM_BLO 49152
#define STAGE_BYTES 65536
#define TG_SMEM (2*STAGE_BYTES)

__global__ __launch_bounds__(256, 1) void tgemm_kernel(
    const bf16* __restrict__ Ahi, const bf16* __restrict__ Alo,
    const bf16* __restrict__ Bhi, const bf16* __restrict__ Blo,
    const float* __restrict__ bias, const float* __restrict__ res,
    float* __restrict__ Cf, bf16* __restrict__ Chi, bf16* __restrict__ Clo,
    int K, int N, int epi)
{
    extern __shared__ char smem[];
    const uint32_t smem_base = smem_u32(smem);
    const int tid  = threadIdx.x;
    const int wid  = tid >> 5;
    const int lane = tid & 31;
    const int bx = blockIdx.x, by = blockIdx.y;
    const int wm = wid & 3;       // 0..3 -> m offset wm*32
    const int wn = wid >> 2;      // 0..1 -> n offset wn*64

    const bf16* Ah = Ahi + (size_t)by * 128 * K;
    const bf16* Al = Alo + (size_t)by * 128 * K;
    const bf16* Bh = Bhi + (size_t)bx * 128 * K;
    const bf16* Bl = Blo + (size_t)bx * 128 * K;

    // staging pattern: thread covers 4 (row, 16B-chunk) pairs per tile
    const int srow = tid >> 3;        // base row (x4 via +32*i)
    const int schk = tid & 7;         // 16B chunk (0..7) within 128B row

    auto stage = [&](int buf, int k0) {
        uint32_t sb = smem_base + buf * STAGE_BYTES;
        #pragma unroll
        for (int i = 0; i < 4; i++) {
            int row = srow + i * 32;
            size_t go = (size_t)row * K + k0 + schk * 8;
            uint32_t so = sw128((uint32_t)(row * 128 + schk * 16));
            cp16(sb + SM_AHI + so, Ah + go);
            cp16(sb + SM_ALO + so, Al + go);
            cp16(sb + SM_BHI + so, Bh + go);
            cp16(sb + SM_BLO + so, Bl + go);
        }
        CP_COMMIT();
    };

    // ldmatrix lane addressing
    const int a_row = (lane & 15);            // + warp m base
    const int a_col = (lane >> 4) * 16;       // byte offset within kstep
    const int b_row = (lane & 7) | ((lane >> 4) << 3);
    const int b_col = ((lane >> 3) & 1) * 16;

    float acc[2][8][4];
    #pragma unroll
    for (int mt = 0; mt < 2; mt++)
        #pragma unroll
        for (int nt = 0; nt < 8; nt++)
            #pragma unroll
            for (int i = 0; i < 4; i++) acc[mt][nt][i] = 0.f;

    const int NC = K >> 6;
    stage(0, 0);

    for (int c = 0; c < NC; c++) {
        if (c + 1 < NC) stage((c + 1) & 1, (c + 1) * 64);
        if (c + 1 < NC) { CP_WAIT(1); } else { CP_WAIT(0); }
        __syncthreads();

        uint32_t sb = smem_base + (c & 1) * STAGE_BYTES;

        #pragma unroll
        for (int ks = 0; ks < 4; ks++) {
            int kb = ks * 32;   // byte offset of kstep within 128B row

            uint32_t ah[2][4], al[2][4];
            #pragma unroll
            for (int mt = 0; mt < 2; mt++) {
                int row = wm * 32 + mt * 16 + a_row;
                uint32_t off = sw128((uint32_t)(row * 128 + kb + a_col));
                LDSM_X4(ah[mt], sb + SM_AHI + off);
                LDSM_X4(al[mt], sb + SM_ALO + off);
            }
            uint32_t bh[4][4], bl[4][4];
            #pragma unroll
            for (int p = 0; p < 4; p++) {
                int row = wn * 64 + p * 16 + b_row;
                uint32_t off = sw128((uint32_t)(row * 128 + kb + b_col));
                LDSM_X4(bh[p], sb + SM_BHI + off);
                LDSM_X4(bl[p], sb + SM_BLO + off);
            }

            #pragma unroll
            for (int mt = 0; mt < 2; mt++)
                #pragma unroll
                for (int p = 0; p < 4; p++)
                    #pragma unroll
                    for (int sub = 0; sub < 2; sub++) {
                        int nt = p * 2 + sub;
                        mma16816(acc[mt][nt], ah[mt], bh[p][sub*2], bh[p][sub*2+1]);
                        mma16816(acc[mt][nt], ah[mt], bl[p][sub*2], bl[p][sub*2+1]);
                        mma16816(acc[mt][nt], al[mt], bh[p][sub*2], bh[p][sub*2+1]);
                    }
        }
        __syncthreads();
    }

    // ---- epilogue ----
    const int lrow = lane >> 2;
    const int lcol = (lane & 3) * 2;

    #pragma unroll
    for (int mt = 0; mt < 2; mt++) {
        #pragma unroll
        for (int nt = 0; nt < 8; nt++) {
            int Rg = by * 128 + wm * 32 + mt * 16 + lrow;
            int Cg = bx * 128 + wn * 64 + nt * 8 + lcol;
            float b0 = bias[Cg], b1 = bias[Cg + 1];
            #pragma unroll
            for (int h = 0; h < 2; h++) {   // h=0: rows lrow, h=1: +8
                int R = Rg + h * 8;
                float v0 = acc[mt][nt][h * 2 + 0] + b0;
                float v1 = acc[mt][nt][h * 2 + 1] + b1;
                if (epi == 1) {
                    float2 rv = *reinterpret_cast<const float2*>(res + (size_t)R * N + Cg);
                    v0 += rv.x; v1 += rv.y;
                }
                if (epi == 2) {
                    v0 = gelu_f(v0); v1 = gelu_f(v1);
                    bf16 h0, l0, h1, l1;
                    split2(v0, h0, l0); split2(v1, h1, l1);
                    __nv_bfloat162 ph; ph.x = h0; ph.y = h1;
                    __nv_bfloat162 pl; pl.x = l0; pl.y = l1;
                    *reinterpret_cast<__nv_bfloat162*>(Chi + (size_t)R * N + Cg) = ph;
                    *reinterpret_cast<__nv_bfloat162*>(Clo + (size_t)R * N + Cg) = pl;
                } else {
                    float2 o; o.x = v0; o.y = v1;
                    *reinterpret_cast<float2*>(Cf + (size_t)R * N + Cg) = o;
                }
            }
        }
    }
}

// ---------------- flash attention (causal, fp32) -> bf16 hi/lo ------------------
#define ATT_STRIDE 65
#define ATT_SMEM   (4 * 64 * ATT_STRIDE * 4)

__global__ void attn_kernel(const float* __restrict__ qkv,
                            bf16* __restrict__ out_hi, bf16* __restrict__ out_lo)
{
    extern __shared__ float sm[];
    float* Qs = sm;
    float* Ks = Qs + 64 * ATT_STRIDE;
    float* Vs = Ks + 64 * ATT_STRIDE;
    float* Ps = Vs + 64 * ATT_STRIDE;

    const int qt  = blockIdx.x;
    const int bh  = blockIdx.y;
    const int bb  = bh >> 4;
    const int hh  = bh & 15;
    const int tid = threadIdx.x;
    const int tq  = tid >> 2;
    const int c   = tid & 3;

    #pragma unroll
    for (int l = 0; l < 16; l++) {
        int idx = l * 256 + tid;
        int r = idx >> 6, col = idx & 63;
        size_t g = ((size_t)(bb * SS + qt * 64 + r)) * D3 + hh * HD + col;
        Qs[r * ATT_STRIDE + col] = qkv[g] * 0.125f;
    }

    float O[16];
    #pragma unroll
    for (int i = 0; i < 16; i++) O[i] = 0.f;
    float mrun = -1e30f, lrun = 0.f;

    for (int kt = 0; kt <= qt; kt++) {
        #pragma unroll
        for (int l = 0; l < 16; l++) {
            int idx = l * 256 + tid;
            int r = idx >> 6, col = idx & 63;
            size_t g = ((size_t)(bb * SS + kt * 64 + r)) * D3 + DD + hh * HD + col;
            Ks[r * ATT_STRIDE + col] = qkv[g];
            Vs[r * ATT_STRIDE + col] = qkv[g + DD];
        }
        __syncthreads();

        float s[16];
        #pragma unroll
        for (int j16 = 0; j16 < 16; j16++) s[j16] = 0.f;
        #pragma unroll 8
        for (int d = 0; d < 64; d++) {
            float qd = Qs[tq * ATT_STRIDE + d];
            #pragma unroll
            for (int j16 = 0; j16 < 16; j16++)
                s[j16] += qd * Ks[(4 * j16 + c) * ATT_STRIDE + d];
        }
        if (kt == qt) {
            #pragma unroll
            for (int j16 = 0; j16 < 16; j16++)
                if (4 * j16 + c > tq) s[j16] = -1e30f;
        }

        float tmax = s[0];
        #pragma unroll
        for (int j16 = 1; j16 < 16; j16++) tmax = fmaxf(tmax, s[j16]);
        tmax = fmaxf(tmax, __shfl_xor_sync(0xffffffffu, tmax, 1));
        tmax = fmaxf(tmax, __shfl_xor_sync(0xffffffffu, tmax, 2));

        float newm = fmaxf(mrun, tmax);
        float corr = __expf(mrun - newm);

        float psum = 0.f;
        #pragma unroll
        for (int j16 = 0; j16 < 16; j16++) {
            float p = __expf(s[j16] - newm);
            s[j16] = p;
            psum += p;
        }
        psum += __shfl_xor_sync(0xffffffffu, psum, 1);
        psum += __shfl_xor_sync(0xffffffffu, psum, 2);
        lrun = lrun * corr + psum;
        mrun = newm;

        #pragma unroll
        for (int dd = 0; dd < 16; dd++) O[dd] *= corr;

        #pragma unroll
        for (int j16 = 0; j16 < 16; j16++)
            Ps[tq * ATT_STRIDE + 4 * j16 + c] = s[j16];
        __syncthreads();

        #pragma unroll 8
        for (int j = 0; j < 64; j++) {
            float p = Ps[tq * ATT_STRIDE + j];
            #pragma unroll
            for (int dd = 0; dd < 16; dd++)
                O[dd] += p * Vs[j * ATT_STRIDE + 4 * dd + c];
        }
        __syncthreads();
    }

    float inv = 1.0f / lrun;
    size_t gq = (size_t)(bb * SS + qt * 64 + tq);
    #pragma unroll
    for (int dd = 0; dd < 16; dd++) {
        float v = O[dd] * inv;
        bf16 h, l; split2(v, h, l);
        size_t o = gq * DD + hh * HD + 4 * dd + c;
        out_hi[o] = h;
        out_lo[o] = l;
    }
}

// ---------------- launcher -----------------------------------------------------
extern "C" void kernel_launch(void* const* d_in, const int* in_sizes, int n_in,
                              void* d_out, int out_size)
{
    const float* x       = (const float*)d_in[0];
    const float* ln1_w   = (const float*)d_in[1];
    const float* ln1_b   = (const float*)d_in[2];
    const float* W_attn  = (const float*)d_in[3];
    const float* b_attn  = (const float*)d_in[4];
    const float* W_cproj = (const float*)d_in[5];
    const float* b_cproj = (const float*)d_in[6];
    const float* ln2_w   = (const float*)d_in[7];
    const float* ln2_b   = (const float*)d_in[8];
    const float* W_fc    = (const float*)d_in[9];
    const float* b_fc    = (const float*)d_in[10];
    const float* W_mproj = (const float*)d_in[11];
    const float* b_mproj = (const float*)d_in[12];
    float* out = (float*)d_out;

    float *qkv, *x2;
    bf16 *h_hi, *h_lo, *att_hi, *att_lo, *m_hi, *m_lo, *fc_hi, *fc_lo, *wt_hi, *wt_lo;
    cudaGetSymbolAddress((void**)&qkv,    g_qkv);
    cudaGetSymbolAddress((void**)&x2,     g_x2);
    cudaGetSymbolAddress((void**)&h_hi,   g_h_hi);
    cudaGetSymbolAddress((void**)&h_lo,   g_h_lo);
    cudaGetSymbolAddress((void**)&att_hi, g_att_hi);
    cudaGetSymbolAddress((void**)&att_lo, g_att_lo);
    cudaGetSymbolAddress((void**)&m_hi,   g_m_hi);
    cudaGetSymbolAddress((void**)&m_lo,   g_m_lo);
    cudaGetSymbolAddress((void**)&fc_hi,  g_fc_hi);
    cudaGetSymbolAddress((void**)&fc_lo,  g_fc_lo);
    cudaGetSymbolAddress((void**)&wt_hi,  g_wt_hi);
    cudaGetSymbolAddress((void**)&wt_lo,  g_wt_lo);

    cudaFuncSetAttribute(attn_kernel,  cudaFuncAttributeMaxDynamicSharedMemorySize, ATT_SMEM);
    cudaFuncSetAttribute(tgemm_kernel, cudaFuncAttributeMaxDynamicSharedMemorySize, TG_SMEM);

    dim3 wblk(32, 8);
    wconv_kernel<<<dim3(D3 / 32, DD / 32), wblk>>>(W_attn,  wt_hi + WATTN_OFF,  wt_lo + WATTN_OFF,  DD, D3);
    wconv_kernel<<<dim3(DD / 32, DD / 32), wblk>>>(W_cproj, wt_hi + WCPROJ_OFF, wt_lo + WCPROJ_OFF, DD, DD);
    wconv_kernel<<<dim3(D4 / 32, DD / 32), wblk>>>(W_fc,    wt_hi + WFC_OFF,    wt_lo + WFC_OFF,    DD, D4);
    wconv_kernel<<<dim3(DD / 32, D4 / 32), wblk>>>(W_mproj, wt_hi + WMPROJ_OFF, wt_lo + WMPROJ_OFF, D4, DD);

    // 1. LN1 -> h (hi/lo)
    ln_kernel<<<NTOK, 256>>>(x, ln1_w, ln1_b, h_hi, h_lo);

    // 2. qkv = h @ W_attn + b_attn
    tgemm_kernel<<<dim3(D3 / 128, NTOK / 128), 256, TG_SMEM>>>(
        h_hi, h_lo, wt_hi + WATTN_OFF, wt_lo + WATTN_OFF,
        b_attn, nullptr, qkv, nullptr, nullptr, DD, D3, 0);

    // 3. attention -> att (hi/lo)
    attn_kernel<<<dim3(SS / 64, BB * HH), 256, ATT_SMEM>>>(qkv, att_hi, att_lo);

    // 4. x2 = att @ W_cproj + b_cproj + x
    tgemm_kernel<<<dim3(DD / 128, NTOK / 128), 256, TG_SMEM>>>(
        att_hi, att_lo, wt_hi + WCPROJ_OFF, wt_lo + WCPROJ_OFF,
        b_cproj, x, x2, nullptr, nullptr, DD, DD, 1);

    // 5. LN2 -> m (hi/lo)
    ln_kernel<<<NTOK, 256>>>(x2, ln2_w, ln2_b, m_hi, m_lo);

    // 6. fc = gelu(m @ W_fc + b_fc) -> bf16 hi/lo
    tgemm_kernel<<<dim3(D4 / 128, NTOK / 128), 256, TG_SMEM>>>(
        m_hi, m_lo, wt_hi + WFC_OFF, wt_lo + WFC_OFF,
        b_fc, nullptr, nullptr, fc_hi, fc_lo, DD, D4, 2);

    // 7. out = fc @ W_mproj + b_mproj + x2
    tgemm_kernel<<<dim3(DD / 128, NTOK / 128), 256, TG_SMEM>>>(
        fc_hi, fc_lo, wt_hi + WMPROJ_OFF, wt_lo + WMPROJ_OFF,
        b_mproj, x2, out, nullptr, nullptr, D4, DD, 1);
}

// round 6
// speedup vs baseline: 4.1538x; 2.0682x over previous
#include <cuda_runtime.h>
#include <cuda_bf16.h>
#include <cstdint>
#include <cstddef>

typedef __nv_bfloat16 bf16;

// Problem constants
#define BB   4
#define SS   2048
#define DD   1024
#define HH   16
#define HD   64
#define NTOK (BB*SS)          // 8192
#define D3   (3*DD)           // 3072
#define D4   (4*DD)           // 4096

// ---------------- scratch (device globals) ------------------------------------
__device__ float g_x2 [NTOK*DD];
__device__ bf16  g_qkv_hi[NTOK*D3], g_qkv_lo[NTOK*D3];
__device__ bf16  g_h_hi [NTOK*DD],  g_h_lo [NTOK*DD];
__device__ bf16  g_att_hi[NTOK*DD], g_att_lo[NTOK*DD];
__device__ bf16  g_m_hi [NTOK*DD],  g_m_lo [NTOK*DD];
__device__ bf16  g_fc_hi[NTOK*D4],  g_fc_lo[NTOK*D4];

// transposed weights (hi/lo): Wt[N][K]
#define WATTN_OFF  0
#define WCPROJ_OFF (DD*D3)
#define WFC_OFF    (WCPROJ_OFF + DD*DD)
#define WMPROJ_OFF (WFC_OFF + DD*D4)
#define WTOTAL     (WMPROJ_OFF + D4*DD)
__device__ bf16 g_wt_hi[WTOTAL], g_wt_lo[WTOTAL];

// ---------------- helpers ------------------------------------------------------
__device__ __forceinline__ uint32_t smem_u32(const void* p) {
    uint32_t a;
    asm("{ .reg .u64 t; cvta.to.shared.u64 t, %1; cvt.u32.u64 %0, t; }" : "=r"(a) : "l"(p));
    return a;
}

__device__ __forceinline__ uint32_t sw128(uint32_t b) { return b ^ ((b >> 3) & 0x70); }

__device__ __forceinline__ void cp16(uint32_t saddr, const void* gaddr) {
    asm volatile("cp.async.cg.shared.global [%0], [%1], 16;" :: "r"(saddr), "l"(gaddr));
}
#define CP_COMMIT() asm volatile("cp.async.commit_group;" ::: "memory")
#define CP_WAIT(n)  asm volatile("cp.async.wait_group %0;" :: "n"(n) : "memory")

#define LDSM_X4(r, addr) \
    asm volatile("ldmatrix.sync.aligned.m8n8.x4.shared.b16 {%0,%1,%2,%3}, [%4];" \
        : "=r"((r)[0]), "=r"((r)[1]), "=r"((r)[2]), "=r"((r)[3]) : "r"(addr))

#define LDSM_X4_T(r, addr) \
    asm volatile("ldmatrix.sync.aligned.m8n8.x4.trans.shared.b16 {%0,%1,%2,%3}, [%4];" \
        : "=r"((r)[0]), "=r"((r)[1]), "=r"((r)[2]), "=r"((r)[3]) : "r"(addr))

__device__ __forceinline__ void mma16816(float* c, const uint32_t* a,
                                         uint32_t b0, uint32_t b1)
{
    asm volatile(
        "mma.sync.aligned.m16n8k16.row.col.f32.bf16.bf16.f32 "
        "{%0,%1,%2,%3}, {%4,%5,%6,%7}, {%8,%9}, {%0,%1,%2,%3};"
        : "+f"(c[0]), "+f"(c[1]), "+f"(c[2]), "+f"(c[3])
        : "r"(a[0]), "r"(a[1]), "r"(a[2]), "r"(a[3]), "r"(b0), "r"(b1));
}

__device__ __forceinline__ void split2(float v, bf16& hi, bf16& lo)
{
    hi = __float2bfloat16(v);
    lo = __float2bfloat16(v - __bfloat162float(hi));
}

__device__ __forceinline__ void split_pack(float a, float b, uint32_t& hi, uint32_t& lo)
{
    bf16 ah = __float2bfloat16(a), bh = __float2bfloat16(b);
    float al = a - __bfloat162float(ah);
    float bl = b - __bfloat162float(bh);
    __nv_bfloat162 H; H.x = ah; H.y = bh;
    __nv_bfloat162 L; L.x = __float2bfloat16(al); L.y = __float2bfloat16(bl);
    hi = *reinterpret_cast<uint32_t*>(&H);
    lo = *reinterpret_cast<uint32_t*>(&L);
}

__device__ __forceinline__ float gelu_f(float v)
{
    float c = 0.7978845608028654f * (v + 0.044715f * v * v * v);
    return 0.5f * v * (1.0f + tanhf(c));
}

// ---------------- weight transpose + split:  W[K][N] -> Wt_hi/lo[N][K] --------
__global__ void wconv_kernel(const float* __restrict__ W, bf16* __restrict__ hi,
                             bf16* __restrict__ lo, int K, int N)
{
    __shared__ float t[32][33];
    int n0 = blockIdx.x * 32, k0 = blockIdx.y * 32;
    int tx = threadIdx.x, ty = threadIdx.y;   // 32 x 8
    #pragma unroll
    for (int i = 0; i < 4; i++)
        t[ty + i * 8][tx] = W[(size_t)(k0 + ty + i * 8) * N + n0 + tx];
    __syncthreads();
    #pragma unroll
    for (int i = 0; i < 4; i++) {
        float v = t[tx][ty + i * 8];
        size_t o = (size_t)(n0 + ty + i * 8) * K + k0 + tx;
        bf16 h, l; split2(v, h, l);
        hi[o] = h; lo[o] = l;
    }
}

// ---------------- layernorm -> bf16 hi/lo --------------------------------------
__global__ void ln_kernel(const float* __restrict__ x, const float* __restrict__ w,
                          const float* __restrict__ b, bf16* __restrict__ hi,
                          bf16* __restrict__ lo)
{
    int row = blockIdx.x;
    int tid = threadIdx.x;
    const float4* xr = reinterpret_cast<const float4*>(x + (size_t)row * DD);
    float4 v = xr[tid];
    float s  = v.x + v.y + v.z + v.w;
    float ss = v.x*v.x + v.y*v.y + v.z*v.z + v.w*v.w;

    __shared__ float red0[8], red1[8], stat[2];
    #pragma unroll
    for (int o = 16; o; o >>= 1) {
        s  += __shfl_xor_sync(0xffffffffu, s,  o);
        ss += __shfl_xor_sync(0xffffffffu, ss, o);
    }
    int wid = tid >> 5, lane = tid & 31;
    if (lane == 0) { red0[wid] = s; red1[wid] = ss; }
    __syncthreads();
    if (tid == 0) {
        float ts = 0.f, tss = 0.f;
        #pragma unroll
        for (int i = 0; i < 8; i++) { ts += red0[i]; tss += red1[i]; }
        float mean = ts * (1.0f / DD);
        float var  = tss * (1.0f / DD) - mean * mean;
        stat[0] = mean;
        stat[1] = rsqrtf(var + 1e-5f);
    }
    __syncthreads();
    float mean = stat[0], rstd = stat[1];

    float4 wv = reinterpret_cast<const float4*>(w)[tid];
    float4 bv = reinterpret_cast<const float4*>(b)[tid];
    float o0 = wv.x * (v.x - mean) * rstd + bv.x;
    float o1 = wv.y * (v.y - mean) * rstd + bv.y;
    float o2 = wv.z * (v.z - mean) * rstd + bv.z;
    float o3 = wv.w * (v.w - mean) * rstd + bv.w;
    bf16 h0,l0,h1,l1,h2,l2,h3,l3;
    split2(o0,h0,l0); split2(o1,h1,l1); split2(o2,h2,l2); split2(o3,h3,l3);
    __nv_bfloat162* Hh = reinterpret_cast<__nv_bfloat162*>(hi + (size_t)row * DD);
    __nv_bfloat162* Hl = reinterpret_cast<__nv_bfloat162*>(lo + (size_t)row * DD);
    __nv_bfloat162 p;
    p.x = h0; p.y = h1; Hh[tid*2]   = p;
    p.x = h2; p.y = h3; Hh[tid*2+1] = p;
    p.x = l0; p.y = l1; Hl[tid*2]   = p;
    p.x = l2; p.y = l3; Hl[tid*2+1] = p;
}

// ---------------- HMMA bf16x3 GEMM ---------------------------------------------
// C[M,N] = A[M,K] @ Bt[N,K]^T, A/Bt as bf16 hi/lo. BM=BN=128, BK=64.
// 256 threads = 8 warps, warp tile 32(m) x 64(n).
// epi: 0 = bias->f32 ; 1 = bias+res->f32 ; 2 = gelu(bias)->bf16 hi/lo
//      3 = bias (Q cols scaled 0.125) -> bf16 hi/lo
#define SM_AHI 0
#define SM_ALO 16384
#define SM_BHI 32768
#define SM_BLO 49152
#define STAGE_BYTES 65536
#define TG_SMEM (2*STAGE_BYTES)

__global__ __launch_bounds__(256, 1) void tgemm_kernel(
    const bf16* __restrict__ Ahi, const bf16* __restrict__ Alo,
    const bf16* __restrict__ Bhi, const bf16* __restrict__ Blo,
    const float* __restrict__ bias, const float* __restrict__ res,
    float* __restrict__ Cf, bf16* __restrict__ Chi, bf16* __restrict__ Clo,
    int K, int N, int epi)
{
    extern __shared__ char smem[];
    const uint32_t smem_base = smem_u32(smem);
    const int tid  = threadIdx.x;
    const int wid  = tid >> 5;
    const int lane = tid & 31;
    const int bx = blockIdx.x, by = blockIdx.y;
    const int wm = wid & 3;
    const int wn = wid >> 2;

    const bf16* Ah = Ahi + (size_t)by * 128 * K;
    const bf16* Al = Alo + (size_t)by * 128 * K;
    const bf16* Bh = Bhi + (size_t)bx * 128 * K;
    const bf16* Bl = Blo + (size_t)bx * 128 * K;

    const int srow = tid >> 3;
    const int schk = tid & 7;

    auto stage = [&](int buf, int k0) {
        uint32_t sb = smem_base + buf * STAGE_BYTES;
        #pragma unroll
        for (int i = 0; i < 4; i++) {
            int row = srow + i * 32;
            size_t go = (size_t)row * K + k0 + schk * 8;
            uint32_t so = sw128((uint32_t)(row * 128 + schk * 16));
            cp16(sb + SM_AHI + so, Ah + go);
            cp16(sb + SM_ALO + so, Al + go);
            cp16(sb + SM_BHI + so, Bh + go);
            cp16(sb + SM_BLO + so, Bl + go);
        }
        CP_COMMIT();
    };

    const int a_row = (lane & 15);
    const int a_col = (lane >> 4) * 16;
    const int b_row = (lane & 7) | ((lane >> 4) << 3);
    const int b_col = ((lane >> 3) & 1) * 16;

    float acc[2][8][4];
    #pragma unroll
    for (int mt = 0; mt < 2; mt++)
        #pragma unroll
        for (int nt = 0; nt < 8; nt++)
            #pragma unroll
            for (int i = 0; i < 4; i++) acc[mt][nt][i] = 0.f;

    const int NC = K >> 6;
    stage(0, 0);

    for (int c = 0; c < NC; c++) {
        if (c + 1 < NC) stage((c + 1) & 1, (c + 1) * 64);
        if (c + 1 < NC) { CP_WAIT(1); } else { CP_WAIT(0); }
        __syncthreads();

        uint32_t sb = smem_base + (c & 1) * STAGE_BYTES;

        #pragma unroll
        for (int ks = 0; ks < 4; ks++) {
            int kb = ks * 32;

            uint32_t ah[2][4], al[2][4];
            #pragma unroll
            for (int mt = 0; mt < 2; mt++) {
                int row = wm * 32 + mt * 16 + a_row;
                uint32_t off = sw128((uint32_t)(row * 128 + kb + a_col));
                LDSM_X4(ah[mt], sb + SM_AHI + off);
                LDSM_X4(al[mt], sb + SM_ALO + off);
            }
            uint32_t bh[4][4], bl[4][4];
            #pragma unroll
            for (int p = 0; p < 4; p++) {
                int row = wn * 64 + p * 16 + b_row;
                uint32_t off = sw128((uint32_t)(row * 128 + kb + b_col));
                LDSM_X4(bh[p], sb + SM_BHI + off);
                LDSM_X4(bl[p], sb + SM_BLO + off);
            }

            #pragma unroll
            for (int mt = 0; mt < 2; mt++)
                #pragma unroll
                for (int p = 0; p < 4; p++)
                    #pragma unroll
                    for (int sub = 0; sub < 2; sub++) {
                        int nt = p * 2 + sub;
                        mma16816(acc[mt][nt], ah[mt], bh[p][sub*2], bh[p][sub*2+1]);
                        mma16816(acc[mt][nt], ah[mt], bl[p][sub*2], bl[p][sub*2+1]);
                        mma16816(acc[mt][nt], al[mt], bh[p][sub*2], bh[p][sub*2+1]);
                    }
        }
        __syncthreads();
    }

    // ---- epilogue ----
    const int lrow = lane >> 2;
    const int lcol = (lane & 3) * 2;

    #pragma unroll
    for (int mt = 0; mt < 2; mt++) {
        #pragma unroll
        for (int nt = 0; nt < 8; nt++) {
            int Rg = by * 128 + wm * 32 + mt * 16 + lrow;
            int Cg = bx * 128 + wn * 64 + nt * 8 + lcol;
            float b0 = bias[Cg], b1 = bias[Cg + 1];
            #pragma unroll
            for (int h = 0; h < 2; h++) {
                int R = Rg + h * 8;
                float v0 = acc[mt][nt][h * 2 + 0] + b0;
                float v1 = acc[mt][nt][h * 2 + 1] + b1;
                if (epi == 1) {
                    float2 rv = *reinterpret_cast<const float2*>(res + (size_t)R * N + Cg);
                    v0 += rv.x; v1 += rv.y;
                }
                if (epi == 2 || epi == 3) {
                    if (epi == 2) { v0 = gelu_f(v0); v1 = gelu_f(v1); }
                    else if (Cg < DD) { v0 *= 0.125f; v1 *= 0.125f; }
                    bf16 h0, l0, h1, l1;
                    split2(v0, h0, l0); split2(v1, h1, l1);
                    __nv_bfloat162 ph; ph.x = h0; ph.y = h1;
                    __nv_bfloat162 pl; pl.x = l0; pl.y = l1;
                    *reinterpret_cast<__nv_bfloat162*>(Chi + (size_t)R * N + Cg) = ph;
                    *reinterpret_cast<__nv_bfloat162*>(Clo + (size_t)R * N + Cg) = pl;
                } else {
                    float2 o; o.x = v0; o.y = v1;
                    *reinterpret_cast<float2*>(Cf + (size_t)R * N + Cg) = o;
                }
            }
        }
    }
}

// ---------------- tensor-core flash attention (causal, bf16x3) ------------------
// grid (S/128, B*H), 256 threads = 8 warps; warp w owns q rows w*16..w*16+15.
// smem: Q hi/lo 128x64, double-buffered K/V hi/lo 64x64 tiles (SW128).
#define AQ_HI 0
#define AQ_LO 16384
#define ABUF  32768        // per buffer: KHI+0, KLO+8192, VHI+16384, VLO+24576
#define ABUF_SZ 32768
#define ATT_SMEM (ABUF + 2*ABUF_SZ)   // 98304

__global__ __launch_bounds__(256, 1) void attn_kernel(
    const bf16* __restrict__ qkv_hi, const bf16* __restrict__ qkv_lo,
    bf16* __restrict__ out_hi, bf16* __restrict__ out_lo)
{
    extern __shared__ char smem[];
    const uint32_t sb = smem_u32(smem);
    const int qt  = blockIdx.x;
    const int bh  = blockIdx.y;
    const int bb  = bh >> 4;
    const int hh  = bh & 15;
    const int tid = threadIdx.x;
    const int w   = tid >> 5;
    const int lane = tid & 31;

    const size_t rowbase = (size_t)bb * SS;
    const int colq = hh * HD;

    // ---- stage Q (128 rows x 64 cols, hi+lo) ----
    #pragma unroll
    for (int t = 0; t < 4; t++) {
        int idx = tid + t * 256;
        int row = idx >> 3, chk = idx & 7;
        size_t g = (rowbase + qt * 128 + row) * D3 + colq + chk * 8;
        uint32_t so = sw128((uint32_t)(row * 128 + chk * 16));
        cp16(sb + AQ_HI + so, qkv_hi + g);
        cp16(sb + AQ_LO + so, qkv_lo + g);
    }

    auto stage_kv = [&](int buf, int kt) {
        uint32_t base = sb + ABUF + buf * ABUF_SZ;
        #pragma unroll
        for (int t = 0; t < 2; t++) {
            int idx = tid + t * 256;
            int row = idx >> 3, chk = idx & 7;
            size_t g = (rowbase + kt * 64 + row) * D3 + DD + colq + chk * 8;
            uint32_t so = sw128((uint32_t)(row * 128 + chk * 16));
            cp16(base + 0     + so, qkv_hi + g);
            cp16(base + 8192  + so, qkv_lo + g);
            cp16(base + 16384 + so, qkv_hi + g + DD);
            cp16(base + 24576 + so, qkv_lo + g + DD);
        }
        CP_COMMIT();
    };

    stage_kv(0, 0);

    // fragment addressing
    const int a_row = lane & 15;
    const int a_col = (lane >> 4) * 16;
    const int b_row = (lane & 7) | ((lane >> 4) << 3);
    const int b_col = ((lane >> 3) & 1) * 16;
    const int vt_row = ((lane >> 3) & 1) * 8 + (lane & 7);
    const int vt_col = ((lane >> 4) & 1) * 16;
    const int r0 = lane >> 2;
    const int c2 = (lane & 3) * 2;

    float oacc[8][4];
    #pragma unroll
    for (int nt = 0; nt < 8; nt++)
        #pragma unroll
        for (int i = 0; i < 4; i++) oacc[nt][i] = 0.f;
    float mrun[2] = {-1e30f, -1e30f}, lrun[2] = {0.f, 0.f};

    const int ktmax = 2 * qt + 1;

    for (int kt = 0; kt <= ktmax; kt++) {
        if (kt < ktmax) { stage_kv((kt + 1) & 1, kt + 1); CP_WAIT(1); }
        else            { CP_WAIT(0); }
        __syncthreads();

        uint32_t kvb = sb + ABUF + (kt & 1) * ABUF_SZ;

        // ---- S = Q @ K^T (bf16x3) ----
        float sacc[8][4];
        #pragma unroll
        for (int nt = 0; nt < 8; nt++)
            #pragma unroll
            for (int i = 0; i < 4; i++) sacc[nt][i] = 0.f;

        #pragma unroll
        for (int ks = 0; ks < 4; ks++) {
            int kb = ks * 32;
            uint32_t qh[4], ql[4];
            {
                int row = w * 16 + a_row;
                uint32_t off = sw128((uint32_t)(row * 128 + kb + a_col));
                LDSM_X4(qh, sb + AQ_HI + off);
                LDSM_X4(ql, sb + AQ_LO + off);
            }
            #pragma unroll
            for (int g = 0; g < 4; g++) {
                uint32_t kh[4], kl[4];
                int row = g * 16 + b_row;
                uint32_t off = sw128((uint32_t)(row * 128 + kb + b_col));
                LDSM_X4(kh, kvb + 0    + off);
                LDSM_X4(kl, kvb + 8192 + off);
                #pragma unroll
                for (int sub = 0; sub < 2; sub++) {
                    int nt = g * 2 + sub;
                    mma16816(sacc[nt], qh, kh[sub*2], kh[sub*2+1]);
                    mma16816(sacc[nt], qh, kl[sub*2], kl[sub*2+1]);
                    mma16816(sacc[nt], ql, kh[sub*2], kh[sub*2+1]);
                }
            }
        }

        // ---- causal mask ----
        if (kt >= 2 * qt) {
            #pragma unroll
            for (int nt = 0; nt < 8; nt++)
                #pragma unroll
                for (int i = 0; i < 4; i++) {
                    int rg = qt * 128 + w * 16 + r0 + (i >> 1) * 8;
                    int cg = kt * 64 + nt * 8 + c2 + (i & 1);
                    if (cg > rg) sacc[nt][i] = -1e30f;
                }
        }

        // ---- online softmax (rows r0 and r0+8 per thread) ----
        float corr[2];
        #pragma unroll
        for (int h = 0; h < 2; h++) {
            float mx = -1e30f;
            #pragma unroll
            for (int nt = 0; nt < 8; nt++) {
                mx = fmaxf(mx, sacc[nt][h*2]);
                mx = fmaxf(mx, sacc[nt][h*2+1]);
            }
            mx = fmaxf(mx, __shfl_xor_sync(0xffffffffu, mx, 1));
            mx = fmaxf(mx, __shfl_xor_sync(0xffffffffu, mx, 2));
            float newm = fmaxf(mrun[h], mx);
            corr[h] = __expf(mrun[h] - newm);
            float ps = 0.f;
            #pragma unroll
            for (int nt = 0; nt < 8; nt++) {
                float p0 = __expf(sacc[nt][h*2]   - newm);
                float p1 = __expf(sacc[nt][h*2+1] - newm);
                sacc[nt][h*2] = p0; sacc[nt][h*2+1] = p1;
                ps += p0 + p1;
            }
            ps += __shfl_xor_sync(0xffffffffu, ps, 1);
            ps += __shfl_xor_sync(0xffffffffu, ps, 2);
            lrun[h] = lrun[h] * corr[h] + ps;
            mrun[h] = newm;
        }
        #pragma unroll
        for (int nt = 0; nt < 8; nt++) {
            oacc[nt][0] *= corr[0]; oacc[nt][1] *= corr[0];
            oacc[nt][2] *= corr[1]; oacc[nt][3] *= corr[1];
        }

        // ---- pack P (C-frag -> A-frag), hi/lo ----
        uint32_t pah[4][4], pal[4][4];
        #pragma unroll
        for (int g = 0; g < 4; g++) {
            split_pack(sacc[2*g][0],   sacc[2*g][1],   pah[g][0], pal[g][0]);
            split_pack(sacc[2*g][2],   sacc[2*g][3],   pah[g][1], pal[g][1]);
            split_pack(sacc[2*g+1][0], sacc[2*g+1][1], pah[g][2], pal[g][2]);
            split_pack(sacc[2*g+1][2], sacc[2*g+1][3], pah[g][3], pal[g][3]);
        }

        // ---- O += P @ V (V via ldmatrix.trans) ----
        #pragma unroll
        for (int ks = 0; ks < 4; ks++) {
            #pragma unroll
            for (int gd = 0; gd < 4; gd++) {
                uint32_t vh[4], vl[4];
                int row = ks * 16 + vt_row;
                uint32_t off = sw128((uint32_t)(row * 128 + gd * 32 + vt_col));
                LDSM_X4_T(vh, kvb + 16384 + off);
                LDSM_X4_T(vl, kvb + 24576 + off);
                #pragma unroll
                for (int sub = 0; sub < 2; sub++) {
                    int ntd = gd * 2 + sub;
                    mma16816(oacc[ntd], pah[ks], vh[sub*2], vh[sub*2+1]);
                    mma16816(oacc[ntd], pah[ks], vl[sub*2], vl[sub*2+1]);
                    mma16816(oacc[ntd], pal[ks], vh[sub*2], vh[sub*2+1]);
                }
            }
        }
        __syncthreads();
    }

    // ---- epilogue ----
    float inv[2] = {1.0f / lrun[0], 1.0f / lrun[1]};
    #pragma unroll
    for (int nt = 0; nt < 8; nt++) {
        #pragma unroll
        for (int h = 0; h < 2; h++) {
            int rg = qt * 128 + w * 16 + r0 + h * 8;
            int cg = colq + nt * 8 + c2;
            float v0 = oacc[nt][h*2]   * inv[h];
            float v1 = oacc[nt][h*2+1] * inv[h];
            bf16 h0, l0, h1, l1;
            split2(v0, h0, l0); split2(v1, h1, l1);
            __nv_bfloat162 ph; ph.x = h0; ph.y = h1;
            __nv_bfloat162 pl; pl.x = l0; pl.y = l1;
            size_t o = (rowbase + rg) * DD + cg;
            *reinterpret_cast<__nv_bfloat162*>(out_hi + o) = ph;
            *reinterpret_cast<__nv_bfloat162*>(out_lo + o) = pl;
        }
    }
}

// ---------------- launcher -----------------------------------------------------
extern "C" void kernel_launch(void* const* d_in, const int* in_sizes, int n_in,
                              void* d_out, int out_size)
{
    const float* x       = (const float*)d_in[0];
    const float* ln1_w   = (const float*)d_in[1];
    const float* ln1_b   = (const float*)d_in[2];
    const float* W_attn  = (const float*)d_in[3];
    const float* b_attn  = (const float*)d_in[4];
    const float* W_cproj = (const float*)d_in[5];
    const float* b_cproj = (const float*)d_in[6];
    const float* ln2_w   = (const float*)d_in[7];
    const float* ln2_b   = (const float*)d_in[8];
    const float* W_fc    = (const float*)d_in[9];
    const float* b_fc    = (const float*)d_in[10];
    const float* W_mproj = (const float*)d_in[11];
    const float* b_mproj = (const float*)d_in[12];
    float* out = (float*)d_out;

    float *x2;
    bf16 *qkv_hi, *qkv_lo, *h_hi, *h_lo, *att_hi, *att_lo, *m_hi, *m_lo,
         *fc_hi, *fc_lo, *wt_hi, *wt_lo;
    cudaGetSymbolAddress((void**)&x2,     g_x2);
    cudaGetSymbolAddress((void**)&qkv_hi, g_qkv_hi);
    cudaGetSymbolAddress((void**)&qkv_lo, g_qkv_lo);
    cudaGetSymbolAddress((void**)&h_hi,   g_h_hi);
    cudaGetSymbolAddress((void**)&h_lo,   g_h_lo);
    cudaGetSymbolAddress((void**)&att_hi, g_att_hi);
    cudaGetSymbolAddress((void**)&att_lo, g_att_lo);
    cudaGetSymbolAddress((void**)&m_hi,   g_m_hi);
    cudaGetSymbolAddress((void**)&m_lo,   g_m_lo);
    cudaGetSymbolAddress((void**)&fc_hi,  g_fc_hi);
    cudaGetSymbolAddress((void**)&fc_lo,  g_fc_lo);
    cudaGetSymbolAddress((void**)&wt_hi,  g_wt_hi);
    cudaGetSymbolAddress((void**)&wt_lo,  g_wt_lo);

    cudaFuncSetAttribute(attn_kernel,  cudaFuncAttributeMaxDynamicSharedMemorySize, ATT_SMEM);
    cudaFuncSetAttribute(tgemm_kernel, cudaFuncAttributeMaxDynamicSharedMemorySize, TG_SMEM);

    dim3 wblk(32, 8);
    wconv_kernel<<<dim3(D3 / 32, DD / 32), wblk>>>(W_attn,  wt_hi + WATTN_OFF,  wt_lo + WATTN_OFF,  DD, D3);
    wconv_kernel<<<dim3(DD / 32, DD / 32), wblk>>>(W_cproj, wt_hi + WCPROJ_OFF, wt_lo + WCPROJ_OFF, DD, DD);
    wconv_kernel<<<dim3(D4 / 32, DD / 32), wblk>>>(W_fc,    wt_hi + WFC_OFF,    wt_lo + WFC_OFF,    DD, D4);
    wconv_kernel<<<dim3(DD / 32, D4 / 32), wblk>>>(W_mproj, wt_hi + WMPROJ_OFF, wt_lo + WMPROJ_OFF, D4, DD);

    // 1. LN1 -> h (hi/lo)
    ln_kernel<<<NTOK, 256>>>(x, ln1_w, ln1_b, h_hi, h_lo);

    // 2. qkv = h @ W_attn + b_attn  -> bf16 hi/lo (Q cols pre-scaled 1/8)
    tgemm_kernel<<<dim3(D3 / 128, NTOK / 128), 256, TG_SMEM>>>(
        h_hi, h_lo, wt_hi + WATTN_OFF, wt_lo + WATTN_OFF,
        b_attn, nullptr, nullptr, qkv_hi, qkv_lo, DD, D3, 3);

    // 3. attention -> att (hi/lo)
    attn_kernel<<<dim3(SS / 128, BB * HH), 256, ATT_SMEM>>>(qkv_hi, qkv_lo, att_hi, att_lo);

    // 4. x2 = att @ W_cproj + b_cproj + x
    tgemm_kernel<<<dim3(DD / 128, NTOK / 128), 256, TG_SMEM>>>(
        att_hi, att_lo, wt_hi + WCPROJ_OFF, wt_lo + WCPROJ_OFF,
        b_cproj, x, x2, nullptr, nullptr, DD, DD, 1);

    // 5. LN2 -> m (hi/lo)
    ln_kernel<<<NTOK, 256>>>(x2, ln2_w, ln2_b, m_hi, m_lo);

    // 6. fc = gelu(m @ W_fc + b_fc) -> bf16 hi/lo
    tgemm_kernel<<<dim3(D4 / 128, NTOK / 128), 256, TG_SMEM>>>(
        m_hi, m_lo, wt_hi + WFC_OFF, wt_lo + WFC_OFF,
        b_fc, nullptr, nullptr, fc_hi, fc_lo, DD, D4, 2);

    // 7. out = fc @ W_mproj + b_mproj + x2
    tgemm_kernel<<<dim3(DD / 128, NTOK / 128), 256, TG_SMEM>>>(
        fc_hi, fc_lo, wt_hi + WMPROJ_OFF, wt_lo + WMPROJ_OFF,
        b_mproj, x2, out, nullptr, nullptr, D4, DD, 1);
}

// round 7
// speedup vs baseline: 4.1854x; 1.0076x over previous
#include <cuda_runtime.h>
#include <cuda_bf16.h>
#include <cstdint>
#include <cstddef>

typedef __nv_bfloat16 bf16;

// Problem constants
#define BB   4
#define SS   2048
#define DD   1024
#define HH   16
#define HD   64
#define NTOK (BB*SS)          // 8192
#define D3   (3*DD)           // 3072
#define D4   (4*DD)           // 4096

// ---------------- scratch (device globals) ------------------------------------
__device__ float g_x2 [NTOK*DD];
__device__ bf16  g_qkv_hi[NTOK*D3], g_qkv_lo[NTOK*D3];
__device__ bf16  g_h_hi [NTOK*DD],  g_h_lo [NTOK*DD];
__device__ bf16  g_att_hi[NTOK*DD], g_att_lo[NTOK*DD];
__device__ bf16  g_m_hi [NTOK*DD],  g_m_lo [NTOK*DD];
__device__ bf16  g_fc_hi[NTOK*D4],  g_fc_lo[NTOK*D4];

// transposed weights (hi/lo): Wt[N][K]
#define WATTN_OFF  0
#define WCPROJ_OFF (DD*D3)
#define WFC_OFF    (WCPROJ_OFF + DD*DD)
#define WMPROJ_OFF (WFC_OFF + DD*D4)
#define WTOTAL     (WMPROJ_OFF + D4*DD)
__device__ bf16 g_wt_hi[WTOTAL], g_wt_lo[WTOTAL];

// ---------------- helpers ------------------------------------------------------
__device__ __forceinline__ uint32_t smem_u32(const void* p) {
    uint32_t a;
    asm("{ .reg .u64 t; cvta.to.shared.u64 t, %1; cvt.u32.u64 %0, t; }" : "=r"(a) : "l"(p));
    return a;
}

__device__ __forceinline__ uint32_t sw128(uint32_t b) { return b ^ ((b >> 3) & 0x70); }

__device__ __forceinline__ void cp16(uint32_t saddr, const void* gaddr) {
    asm volatile("cp.async.cg.shared.global [%0], [%1], 16;" :: "r"(saddr), "l"(gaddr));
}
#define CP_COMMIT() asm volatile("cp.async.commit_group;" ::: "memory")
#define CP_WAIT(n)  asm volatile("cp.async.wait_group %0;" :: "n"(n) : "memory")

#define LDSM_X4(r, addr) \
    asm volatile("ldmatrix.sync.aligned.m8n8.x4.shared.b16 {%0,%1,%2,%3}, [%4];" \
        : "=r"((r)[0]), "=r"((r)[1]), "=r"((r)[2]), "=r"((r)[3]) : "r"(addr))

#define LDSM_X4_T(r, addr) \
    asm volatile("ldmatrix.sync.aligned.m8n8.x4.trans.shared.b16 {%0,%1,%2,%3}, [%4];" \
        : "=r"((r)[0]), "=r"((r)[1]), "=r"((r)[2]), "=r"((r)[3]) : "r"(addr))

__device__ __forceinline__ void mma16816(float* c, const uint32_t* a,
                                         uint32_t b0, uint32_t b1)
{
    asm volatile(
        "mma.sync.aligned.m16n8k16.row.col.f32.bf16.bf16.f32 "
        "{%0,%1,%2,%3}, {%4,%5,%6,%7}, {%8,%9}, {%0,%1,%2,%3};"
        : "+f"(c[0]), "+f"(c[1]), "+f"(c[2]), "+f"(c[3])
        : "r"(a[0]), "r"(a[1]), "r"(a[2]), "r"(a[3]), "r"(b0), "r"(b1));
}

__device__ __forceinline__ void split2(float v, bf16& hi, bf16& lo)
{
    hi = __float2bfloat16(v);
    lo = __float2bfloat16(v - __bfloat162float(hi));
}

__device__ __forceinline__ void split_pack(float a, float b, uint32_t& hi, uint32_t& lo)
{
    bf16 ah = __float2bfloat16(a), bh = __float2bfloat16(b);
    float al = a - __bfloat162float(ah);
    float bl = b - __bfloat162float(bh);
    __nv_bfloat162 H; H.x = ah; H.y = bh;
    __nv_bfloat162 L; L.x = __float2bfloat16(al); L.y = __float2bfloat16(bl);
    hi = *reinterpret_cast<uint32_t*>(&H);
    lo = *reinterpret_cast<uint32_t*>(&L);
}

__device__ __forceinline__ float gelu_f(float v)
{
    float c = 0.7978845608028654f * (v + 0.044715f * v * v * v);
    return 0.5f * v * (1.0f + tanhf(c));
}

// ---------------- weight transpose + split:  W[K][N] -> Wt_hi/lo[N][K] --------
__global__ void wconv_kernel(const float* __restrict__ W, bf16* __restrict__ hi,
                             bf16* __restrict__ lo, int K, int N)
{
    __shared__ float t[32][33];
    int n0 = blockIdx.x * 32, k0 = blockIdx.y * 32;
    int tx = threadIdx.x, ty = threadIdx.y;   // 32 x 8
    #pragma unroll
    for (int i = 0; i < 4; i++)
        t[ty + i * 8][tx] = W[(size_t)(k0 + ty + i * 8) * N + n0 + tx];
    __syncthreads();
    #pragma unroll
    for (int i = 0; i < 4; i++) {
        float v = t[tx][ty + i * 8];
        size_t o = (size_t)(n0 + ty + i * 8) * K + k0 + tx;
        bf16 h, l; split2(v, h, l);
        hi[o] = h; lo[o] = l;
    }
}

// ---------------- layernorm -> bf16 hi/lo --------------------------------------
__global__ void ln_kernel(const float* __restrict__ x, const float* __restrict__ w,
                          const float* __restrict__ b, bf16* __restrict__ hi,
                          bf16* __restrict__ lo)
{
    int row = blockIdx.x;
    int tid = threadIdx.x;
    const float4* xr = reinterpret_cast<const float4*>(x + (size_t)row * DD);
    float4 v = xr[tid];
    float s  = v.x + v.y + v.z + v.w;
    float ss = v.x*v.x + v.y*v.y + v.z*v.z + v.w*v.w;

    __shared__ float red0[8], red1[8], stat[2];
    #pragma unroll
    for (int o = 16; o; o >>= 1) {
        s  += __shfl_xor_sync(0xffffffffu, s,  o);
        ss += __shfl_xor_sync(0xffffffffu, ss, o);
    }
    int wid = tid >> 5, lane = tid & 31;
    if (lane == 0) { red0[wid] = s; red1[wid] = ss; }
    __syncthreads();
    if (tid == 0) {
        float ts = 0.f, tss = 0.f;
        #pragma unroll
        for (int i = 0; i < 8; i++) { ts += red0[i]; tss += red1[i]; }
        float mean = ts * (1.0f / DD);
        float var  = tss * (1.0f / DD) - mean * mean;
        stat[0] = mean;
        stat[1] = rsqrtf(var + 1e-5f);
    }
    __syncthreads();
    float mean = stat[0], rstd = stat[1];

    float4 wv = reinterpret_cast<const float4*>(w)[tid];
    float4 bv = reinterpret_cast<const float4*>(b)[tid];
    float o0 = wv.x * (v.x - mean) * rstd + bv.x;
    float o1 = wv.y * (v.y - mean) * rstd + bv.y;
    float o2 = wv.z * (v.z - mean) * rstd + bv.z;
    float o3 = wv.w * (v.w - mean) * rstd + bv.w;
    bf16 h0,l0,h1,l1,h2,l2,h3,l3;
    split2(o0,h0,l0); split2(o1,h1,l1); split2(o2,h2,l2); split2(o3,h3,l3);
    __nv_bfloat162* Hh = reinterpret_cast<__nv_bfloat162*>(hi + (size_t)row * DD);
    __nv_bfloat162* Hl = reinterpret_cast<__nv_bfloat162*>(lo + (size_t)row * DD);
    __nv_bfloat162 p;
    p.x = h0; p.y = h1; Hh[tid*2]   = p;
    p.x = h2; p.y = h3; Hh[tid*2+1] = p;
    p.x = l0; p.y = l1; Hl[tid*2]   = p;
    p.x = l2; p.y = l3; Hl[tid*2+1] = p;
}

// ---------------- HMMA bf16x3 GEMM (3-stage, term-reordered) --------------------
// C[M,N] = A[M,K] @ Bt[N,K]^T, A/Bt as bf16 hi/lo. BM=BN=128, BK=64.
// 256 threads = 8 warps, warp tile 32(m) x 64(n). 3 smem stages.
// EPI: 0 = bias->f32 ; 1 = bias+res->f32 ; 2 = gelu(bias)->bf16 hi/lo
//      3 = bias (Q cols scaled 0.125) -> bf16 hi/lo
#define SM_AHI 0
#define SM_ALO 16384
#define SM_BHI 32768
#define SM_BLO 49152
#define STAGE_BYTES 65536
#define TG_SMEM (3*STAGE_BYTES)

template<int K, int EPI>
__global__ __launch_bounds__(256, 1) void tgemm_kernel(
    const bf16* __restrict__ Ahi, const bf16* __restrict__ Alo,
    const bf16* __restrict__ Bhi, const bf16* __restrict__ Blo,
    const float* __restrict__ bias, const float* __restrict__ res,
    float* __restrict__ Cf, bf16* __restrict__ Chi, bf16* __restrict__ Clo,
    int N)
{
    extern __shared__ char smem[];
    const uint32_t smem_base = smem_u32(smem);
    const int tid  = threadIdx.x;
    const int wid  = tid >> 5;
    const int lane = tid & 31;
    const int bx = blockIdx.x, by = blockIdx.y;
    const int wm = wid & 3;
    const int wn = wid >> 2;

    const bf16* Ah = Ahi + (size_t)by * 128 * K;
    const bf16* Al = Alo + (size_t)by * 128 * K;
    const bf16* Bh = Bhi + (size_t)bx * 128 * K;
    const bf16* Bl = Blo + (size_t)bx * 128 * K;

    const int srow = tid >> 3;
    const int schk = tid & 7;

    auto stage = [&](int buf, int k0) {
        uint32_t sb = smem_base + buf * STAGE_BYTES;
        #pragma unroll
        for (int i = 0; i < 4; i++) {
            int row = srow + i * 32;
            size_t go = (size_t)row * K + k0 + schk * 8;
            uint32_t so = sw128((uint32_t)(row * 128 + schk * 16));
            cp16(sb + SM_AHI + so, Ah + go);
            cp16(sb + SM_ALO + so, Al + go);
            cp16(sb + SM_BHI + so, Bh + go);
            cp16(sb + SM_BLO + so, Bl + go);
        }
        CP_COMMIT();
    };

    const int a_row = (lane & 15);
    const int a_col = (lane >> 4) * 16;
    const int b_row = (lane & 7) | ((lane >> 4) << 3);
    const int b_col = ((lane >> 3) & 1) * 16;

    float acc[2][8][4];
    #pragma unroll
    for (int mt = 0; mt < 2; mt++)
        #pragma unroll
        for (int nt = 0; nt < 8; nt++)
            #pragma unroll
            for (int i = 0; i < 4; i++) acc[mt][nt][i] = 0.f;

    constexpr int NC = K >> 6;
    stage(0, 0);
    stage(1, 64);

    #pragma unroll 1
    for (int c = 0; c < NC; c++) {
        if (c < NC - 1) { CP_WAIT(1); } else { CP_WAIT(0); }
        __syncthreads();
        if (c + 2 < NC) stage((c + 2) % 3, (c + 2) * 64);

        uint32_t sb = smem_base + (c % 3) * STAGE_BYTES;

        #pragma unroll
        for (int ks = 0; ks < 4; ks++) {
            int kb = ks * 32;

            uint32_t ah[2][4], al[2][4];
            #pragma unroll
            for (int mt = 0; mt < 2; mt++) {
                int row = wm * 32 + mt * 16 + a_row;
                uint32_t off = sw128((uint32_t)(row * 128 + kb + a_col));
                LDSM_X4(ah[mt], sb + SM_AHI + off);
                LDSM_X4(al[mt], sb + SM_ALO + off);
            }
            uint32_t bh[4][4], bl[4][4];
            #pragma unroll
            for (int p = 0; p < 4; p++) {
                int row = wn * 64 + p * 16 + b_row;
                uint32_t off = sw128((uint32_t)(row * 128 + kb + b_col));
                LDSM_X4(bh[p], sb + SM_BHI + off);
                LDSM_X4(bl[p], sb + SM_BLO + off);
            }

            // term hh: 16 independent MMAs
            #pragma unroll
            for (int mt = 0; mt < 2; mt++)
                #pragma unroll
                for (int p = 0; p < 4; p++) {
                    mma16816(acc[mt][2*p],   ah[mt], bh[p][0], bh[p][1]);
                    mma16816(acc[mt][2*p+1], ah[mt], bh[p][2], bh[p][3]);
                }
            // term hl
            #pragma unroll
            for (int mt = 0; mt < 2; mt++)
                #pragma unroll
                for (int p = 0; p < 4; p++) {
                    mma16816(acc[mt][2*p],   ah[mt], bl[p][0], bl[p][1]);
                    mma16816(acc[mt][2*p+1], ah[mt], bl[p][2], bl[p][3]);
                }
            // term lh
            #pragma unroll
            for (int mt = 0; mt < 2; mt++)
                #pragma unroll
                for (int p = 0; p < 4; p++) {
                    mma16816(acc[mt][2*p],   al[mt], bh[p][0], bh[p][1]);
                    mma16816(acc[mt][2*p+1], al[mt], bh[p][2], bh[p][3]);
                }
        }
    }

    // ---- epilogue ----
    const int lrow = lane >> 2;
    const int lcol = (lane & 3) * 2;

    #pragma unroll
    for (int mt = 0; mt < 2; mt++) {
        #pragma unroll
        for (int nt = 0; nt < 8; nt++) {
            int Rg = by * 128 + wm * 32 + mt * 16 + lrow;
            int Cg = bx * 128 + wn * 64 + nt * 8 + lcol;
            float b0 = bias[Cg], b1 = bias[Cg + 1];
            #pragma unroll
            for (int h = 0; h < 2; h++) {
                int R = Rg + h * 8;
                float v0 = acc[mt][nt][h * 2 + 0] + b0;
                float v1 = acc[mt][nt][h * 2 + 1] + b1;
                if (EPI == 1) {
                    float2 rv = *reinterpret_cast<const float2*>(res + (size_t)R * N + Cg);
                    v0 += rv.x; v1 += rv.y;
                }
                if (EPI == 2 || EPI == 3) {
                    if (EPI == 2) { v0 = gelu_f(v0); v1 = gelu_f(v1); }
                    else if (Cg < DD) { v0 *= 0.125f; v1 *= 0.125f; }
                    bf16 h0, l0, h1, l1;
                    split2(v0, h0, l0); split2(v1, h1, l1);
                    __nv_bfloat162 ph; ph.x = h0; ph.y = h1;
                    __nv_bfloat162 pl; pl.x = l0; pl.y = l1;
                    *reinterpret_cast<__nv_bfloat162*>(Chi + (size_t)R * N + Cg) = ph;
                    *reinterpret_cast<__nv_bfloat162*>(Clo + (size_t)R * N + Cg) = pl;
                } else {
                    float2 o; o.x = v0; o.y = v1;
                    *reinterpret_cast<float2*>(Cf + (size_t)R * N + Cg) = o;
                }
            }
        }
    }
}

// ---------------- tensor-core flash attention (causal, bf16x3) ------------------
// grid (S/128, B*H), 256 threads = 8 warps; warp w owns q rows w*16..w*16+15.
// smem: Q hi/lo 128x64, 3-stage K/V hi/lo 64x64 tiles (SW128).
#define AQ_HI 0
#define AQ_LO 16384
#define ABUF  32768        // per buffer: KHI+0, KLO+8192, VHI+16384, VLO+24576
#define ABUF_SZ 32768
#define ATT_SMEM (ABUF + 3*ABUF_SZ)   // 131072

__global__ __launch_bounds__(256, 1) void attn_kernel(
    const bf16* __restrict__ qkv_hi, const bf16* __restrict__ qkv_lo,
    bf16* __restrict__ out_hi, bf16* __restrict__ out_lo)
{
    extern __shared__ char smem[];
    const uint32_t sb = smem_u32(smem);
    const int qt  = blockIdx.x;
    const int bh  = blockIdx.y;
    const int bb  = bh >> 4;
    const int hh  = bh & 15;
    const int tid = threadIdx.x;
    const int w   = tid >> 5;
    const int lane = tid & 31;

    const size_t rowbase = (size_t)bb * SS;
    const int colq = hh * HD;

    // ---- stage Q (128 rows x 64 cols, hi+lo); committed with KV tile 0 ----
    #pragma unroll
    for (int t = 0; t < 4; t++) {
        int idx = tid + t * 256;
        int row = idx >> 3, chk = idx & 7;
        size_t g = (rowbase + qt * 128 + row) * D3 + colq + chk * 8;
        uint32_t so = sw128((uint32_t)(row * 128 + chk * 16));
        cp16(sb + AQ_HI + so, qkv_hi + g);
        cp16(sb + AQ_LO + so, qkv_lo + g);
    }

    auto stage_kv = [&](int buf, int kt) {
        uint32_t base = sb + ABUF + buf * ABUF_SZ;
        #pragma unroll
        for (int t = 0; t < 2; t++) {
            int idx = tid + t * 256;
            int row = idx >> 3, chk = idx & 7;
            size_t g = (rowbase + kt * 64 + row) * D3 + DD + colq + chk * 8;
            uint32_t so = sw128((uint32_t)(row * 128 + chk * 16));
            cp16(base + 0     + so, qkv_hi + g);
            cp16(base + 8192  + so, qkv_lo + g);
            cp16(base + 16384 + so, qkv_hi + g + DD);
            cp16(base + 24576 + so, qkv_lo + g + DD);
        }
        CP_COMMIT();
    };

    const int ktmax = 2 * qt + 1;
    stage_kv(0, 0);
    stage_kv(1, 1);   // ktmax >= 1 always

    // fragment addressing
    const int a_row = lane & 15;
    const int a_col = (lane >> 4) * 16;
    const int b_row = (lane & 7) | ((lane >> 4) << 3);
    const int b_col = ((lane >> 3) & 1) * 16;
    const int vt_row = ((lane >> 3) & 1) * 8 + (lane & 7);
    const int vt_col = ((lane >> 4) & 1) * 16;
    const int r0 = lane >> 2;
    const int c2 = (lane & 3) * 2;

    float oacc[8][4];
    #pragma unroll
    for (int nt = 0; nt < 8; nt++)
        #pragma unroll
        for (int i = 0; i < 4; i++) oacc[nt][i] = 0.f;
    float mrun[2] = {-1e30f, -1e30f}, lrun[2] = {0.f, 0.f};

    #pragma unroll 1
    for (int kt = 0; kt <= ktmax; kt++) {
        if (kt < ktmax) { CP_WAIT(1); } else { CP_WAIT(0); }
        __syncthreads();
        if (kt + 2 <= ktmax) stage_kv((kt + 2) % 3, kt + 2);

        uint32_t kvb = sb + ABUF + (kt % 3) * ABUF_SZ;

        // ---- S = Q @ K^T (bf16x3, term-reordered) ----
        float sacc[8][4];
        #pragma unroll
        for (int nt = 0; nt < 8; nt++)
            #pragma unroll
            for (int i = 0; i < 4; i++) sacc[nt][i] = 0.f;

        #pragma unroll
        for (int ks = 0; ks < 4; ks++) {
            int kb = ks * 32;
            uint32_t qh[4], ql[4];
            {
                int row = w * 16 + a_row;
                uint32_t off = sw128((uint32_t)(row * 128 + kb + a_col));
                LDSM_X4(qh, sb + AQ_HI + off);
                LDSM_X4(ql, sb + AQ_LO + off);
            }
            uint32_t kh[4][4], kl[4][4];
            #pragma unroll
            for (int g = 0; g < 4; g++) {
                int row = g * 16 + b_row;
                uint32_t off = sw128((uint32_t)(row * 128 + kb + b_col));
                LDSM_X4(kh[g], kvb + 0    + off);
                LDSM_X4(kl[g], kvb + 8192 + off);
            }
            #pragma unroll
            for (int g = 0; g < 4; g++) {
                mma16816(sacc[2*g],   qh, kh[g][0], kh[g][1]);
                mma16816(sacc[2*g+1], qh, kh[g][2], kh[g][3]);
            }
            #pragma unroll
            for (int g = 0; g < 4; g++) {
                mma16816(sacc[2*g],   qh, kl[g][0], kl[g][1]);
                mma16816(sacc[2*g+1], qh, kl[g][2], kl[g][3]);
            }
            #pragma unroll
            for (int g = 0; g < 4; g++) {
                mma16816(sacc[2*g],   ql, kh[g][0], kh[g][1]);
                mma16816(sacc[2*g+1], ql, kh[g][2], kh[g][3]);
            }
        }

        // ---- causal mask ----
        if (kt >= 2 * qt) {
            #pragma unroll
            for (int nt = 0; nt < 8; nt++)
                #pragma unroll
                for (int i = 0; i < 4; i++) {
                    int rg = qt * 128 + w * 16 + r0 + (i >> 1) * 8;
                    int cg = kt * 64 + nt * 8 + c2 + (i & 1);
                    if (cg > rg) sacc[nt][i] = -1e30f;
                }
        }

        // ---- online softmax (rows r0 and r0+8 per thread) ----
        float corr[2];
        #pragma unroll
        for (int h = 0; h < 2; h++) {
            float mx = -1e30f;
            #pragma unroll
            for (int nt = 0; nt < 8; nt++) {
                mx = fmaxf(mx, sacc[nt][h*2]);
                mx = fmaxf(mx, sacc[nt][h*2+1]);
            }
            mx = fmaxf(mx, __shfl_xor_sync(0xffffffffu, mx, 1));
            mx = fmaxf(mx, __shfl_xor_sync(0xffffffffu, mx, 2));
            float newm = fmaxf(mrun[h], mx);
            corr[h] = __expf(mrun[h] - newm);
            float ps = 0.f;
            #pragma unroll
            for (int nt = 0; nt < 8; nt++) {
                float p0 = __expf(sacc[nt][h*2]   - newm);
                float p1 = __expf(sacc[nt][h*2+1] - newm);
                sacc[nt][h*2] = p0; sacc[nt][h*2+1] = p1;
                ps += p0 + p1;
            }
            ps += __shfl_xor_sync(0xffffffffu, ps, 1);
            ps += __shfl_xor_sync(0xffffffffu, ps, 2);
            lrun[h] = lrun[h] * corr[h] + ps;
            mrun[h] = newm;
        }
        #pragma unroll
        for (int nt = 0; nt < 8; nt++) {
            oacc[nt][0] *= corr[0]; oacc[nt][1] *= corr[0];
            oacc[nt][2] *= corr[1]; oacc[nt][3] *= corr[1];
        }

        // ---- pack P (C-frag -> A-frag), hi/lo ----
        uint32_t pah[4][4], pal[4][4];
        #pragma unroll
        for (int g = 0; g < 4; g++) {
            split_pack(sacc[2*g][0],   sacc[2*g][1],   pah[g][0], pal[g][0]);
            split_pack(sacc[2*g][2],   sacc[2*g][3],   pah[g][1], pal[g][1]);
            split_pack(sacc[2*g+1][0], sacc[2*g+1][1], pah[g][2], pal[g][2]);
            split_pack(sacc[2*g+1][2], sacc[2*g+1][3], pah[g][3], pal[g][3]);
        }

        // ---- O += P @ V (V via ldmatrix.trans, term-reordered) ----
        #pragma unroll
        for (int ks = 0; ks < 4; ks++) {
            uint32_t vh[4][4], vl[4][4];
            #pragma unroll
            for (int gd = 0; gd < 4; gd++) {
                int row = ks * 16 + vt_row;
                uint32_t off = sw128((uint32_t)(row * 128 + gd * 32 + vt_col));
                LDSM_X4_T(vh[gd], kvb + 16384 + off);
                LDSM_X4_T(vl[gd], kvb + 24576 + off);
            }
            #pragma unroll
            for (int gd = 0; gd < 4; gd++) {
                mma16816(oacc[2*gd],   pah[ks], vh[gd][0], vh[gd][1]);
                mma16816(oacc[2*gd+1], pah[ks], vh[gd][2], vh[gd][3]);
            }
            #pragma unroll
            for (int gd = 0; gd < 4; gd++) {
                mma16816(oacc[2*gd],   pah[ks], vl[gd][0], vl[gd][1]);
                mma16816(oacc[2*gd+1], pah[ks], vl[gd][2], vl[gd][3]);
            }
            #pragma unroll
            for (int gd = 0; gd < 4; gd++) {
                mma16816(oacc[2*gd],   pal[ks], vh[gd][0], vh[gd][1]);
                mma16816(oacc[2*gd+1], pal[ks], vh[gd][2], vh[gd][3]);
            }
        }
    }

    // ---- epilogue ----
    float inv[2] = {1.0f / lrun[0], 1.0f / lrun[1]};
    #pragma unroll
    for (int nt = 0; nt < 8; nt++) {
        #pragma unroll
        for (int h = 0; h < 2; h++) {
            int rg = qt * 128 + w * 16 + r0 + h * 8;
            int cg = colq + nt * 8 + c2;
            float v0 = oacc[nt][h*2]   * inv[h];
            float v1 = oacc[nt][h*2+1] * inv[h];
            bf16 h0, l0, h1, l1;
            split2(v0, h0, l0); split2(v1, h1, l1);
            __nv_bfloat162 ph; ph.x = h0; ph.y = h1;
            __nv_bfloat162 pl; pl.x = l0; pl.y = l1;
            size_t o = (rowbase + rg) * DD + cg;
            *reinterpret_cast<__nv_bfloat162*>(out_hi + o) = ph;
            *reinterpret_cast<__nv_bfloat162*>(out_lo + o) = pl;
        }
    }
}

// ---------------- launcher -----------------------------------------------------
extern "C" void kernel_launch(void* const* d_in, const int* in_sizes, int n_in,
                              void* d_out, int out_size)
{
    const float* x       = (const float*)d_in[0];
    const float* ln1_w   = (const float*)d_in[1];
    const float* ln1_b   = (const float*)d_in[2];
    const float* W_attn  = (const float*)d_in[3];
    const float* b_attn  = (const float*)d_in[4];
    const float* W_cproj = (const float*)d_in[5];
    const float* b_cproj = (const float*)d_in[6];
    const float* ln2_w   = (const float*)d_in[7];
    const float* ln2_b   = (const float*)d_in[8];
    const float* W_fc    = (const float*)d_in[9];
    const float* b_fc    = (const float*)d_in[10];
    const float* W_mproj = (const float*)d_in[11];
    const float* b_mproj = (const float*)d_in[12];
    float* out = (float*)d_out;

    float *x2;
    bf16 *qkv_hi, *qkv_lo, *h_hi, *h_lo, *att_hi, *att_lo, *m_hi, *m_lo,
         *fc_hi, *fc_lo, *wt_hi, *wt_lo;
    cudaGetSymbolAddress((void**)&x2,     g_x2);
    cudaGetSymbolAddress((void**)&qkv_hi, g_qkv_hi);
    cudaGetSymbolAddress((void**)&qkv_lo, g_qkv_lo);
    cudaGetSymbolAddress((void**)&h_hi,   g_h_hi);
    cudaGetSymbolAddress((void**)&h_lo,   g_h_lo);
    cudaGetSymbolAddress((void**)&att_hi, g_att_hi);
    cudaGetSymbolAddress((void**)&att_lo, g_att_lo);
    cudaGetSymbolAddress((void**)&m_hi,   g_m_hi);
    cudaGetSymbolAddress((void**)&m_lo,   g_m_lo);
    cudaGetSymbolAddress((void**)&fc_hi,  g_fc_hi);
    cudaGetSymbolAddress((void**)&fc_lo,  g_fc_lo);
    cudaGetSymbolAddress((void**)&wt_hi,  g_wt_hi);
    cudaGetSymbolAddress((void**)&wt_lo,  g_wt_lo);

    cudaFuncSetAttribute(attn_kernel, cudaFuncAttributeMaxDynamicSharedMemorySize, ATT_SMEM);
    cudaFuncSetAttribute(tgemm_kernel<DD,3>, cudaFuncAttributeMaxDynamicSharedMemorySize, TG_SMEM);
    cudaFuncSetAttribute(tgemm_kernel<DD,1>, cudaFuncAttributeMaxDynamicSharedMemorySize, TG_SMEM);
    cudaFuncSetAttribute(tgemm_kernel<DD,2>, cudaFuncAttributeMaxDynamicSharedMemorySize, TG_SMEM);
    cudaFuncSetAttribute(tgemm_kernel<D4,1>, cudaFuncAttributeMaxDynamicSharedMemorySize, TG_SMEM);

    dim3 wblk(32, 8);
    wconv_kernel<<<dim3(D3 / 32, DD / 32), wblk>>>(W_attn,  wt_hi + WATTN_OFF,  wt_lo + WATTN_OFF,  DD, D3);
    wconv_kernel<<<dim3(DD / 32, DD / 32), wblk>>>(W_cproj, wt_hi + WCPROJ_OFF, wt_lo + WCPROJ_OFF, DD, DD);
    wconv_kernel<<<dim3(D4 / 32, DD / 32), wblk>>>(W_fc,    wt_hi + WFC_OFF,    wt_lo + WFC_OFF,    DD, D4);
    wconv_kernel<<<dim3(DD / 32, D4 / 32), wblk>>>(W_mproj, wt_hi + WMPROJ_OFF, wt_lo + WMPROJ_OFF, D4, DD);

    // 1. LN1 -> h (hi/lo)
    ln_kernel<<<NTOK, 256>>>(x, ln1_w, ln1_b, h_hi, h_lo);

    // 2. qkv = h @ W_attn + b_attn  -> bf16 hi/lo (Q cols pre-scaled 1/8)
    tgemm_kernel<DD,3><<<dim3(D3 / 128, NTOK / 128), 256, TG_SMEM>>>(
        h_hi, h_lo, wt_hi + WATTN_OFF, wt_lo + WATTN_OFF,
        b_attn, nullptr, nullptr, qkv_hi, qkv_lo, D3);

    // 3. attention -> att (hi/lo)
    attn_kernel<<<dim3(SS / 128, BB * HH), 256, ATT_SMEM>>>(qkv_hi, qkv_lo, att_hi, att_lo);

    // 4. x2 = att @ W_cproj + b_cproj + x
    tgemm_kernel<DD,1><<<dim3(DD / 128, NTOK / 128), 256, TG_SMEM>>>(
        att_hi, att_lo, wt_hi + WCPROJ_OFF, wt_lo + WCPROJ_OFF,
        b_cproj, x, x2, nullptr, nullptr, DD);

    // 5. LN2 -> m (hi/lo)
    ln_kernel<<<NTOK, 256>>>(x2, ln2_w, ln2_b, m_hi, m_lo);

    // 6. fc = gelu(m @ W_fc + b_fc) -> bf16 hi/lo
    tgemm_kernel<DD,2><<<dim3(D4 / 128, NTOK / 128), 256, TG_SMEM>>>(
        m_hi, m_lo, wt_hi + WFC_OFF, wt_lo + WFC_OFF,
        b_fc, nullptr, nullptr, fc_hi, fc_lo, D4);

    // 7. out = fc @ W_mproj + b_mproj + x2
    tgemm_kernel<D4,1><<<dim3(DD / 128, NTOK / 128), 256, TG_SMEM>>>(
        fc_hi, fc_lo, wt_hi + WMPROJ_OFF, wt_lo + WMPROJ_OFF,
        b_mproj, x2, out, nullptr, nullptr, DD);
}

// round 8
// speedup vs baseline: 5.7870x; 1.3827x over previous
#include <cuda_runtime.h>
#include <cuda_fp16.h>
#include <cstdint>
#include <cstddef>

typedef __half fp16;

// Problem constants
#define BB   4
#define SS   2048
#define DD   1024
#define HH   16
#define HD   64
#define NTOK (BB*SS)          // 8192
#define D3   (3*DD)           // 3072
#define D4   (4*DD)           // 4096

// ---------------- scratch (device globals) ------------------------------------
__device__ float g_x2 [NTOK*DD];
__device__ fp16  g_qkv_hi[NTOK*D3], g_qkv_lo[NTOK*D3];   // lo used only for K/V cols
__device__ fp16  g_h  [NTOK*DD];    // LN1 out (hi only; A-side)
__device__ fp16  g_att[NTOK*DD];    // attention out (hi only; A-side)
__device__ fp16  g_m  [NTOK*DD];    // LN2 out (hi only)
__device__ fp16  g_fc [NTOK*D4];    // gelu out (hi only)

// transposed weights (hi/lo): Wt[N][K]
#define WATTN_OFF  0
#define WCPROJ_OFF (DD*D3)
#define WFC_OFF    (WCPROJ_OFF + DD*DD)
#define WMPROJ_OFF (WFC_OFF + DD*D4)
#define WTOTAL     (WMPROJ_OFF + D4*DD)
__device__ fp16 g_wt_hi[WTOTAL], g_wt_lo[WTOTAL];

// ---------------- helpers ------------------------------------------------------
__device__ __forceinline__ uint32_t smem_u32(const void* p) {
    uint32_t a;
    asm("{ .reg .u64 t; cvta.to.shared.u64 t, %1; cvt.u32.u64 %0, t; }" : "=r"(a) : "l"(p));
    return a;
}

__device__ __forceinline__ uint32_t sw128(uint32_t b) { return b ^ ((b >> 3) & 0x70); }

__device__ __forceinline__ void cp16(uint32_t saddr, const void* gaddr) {
    asm volatile("cp.async.cg.shared.global [%0], [%1], 16;" :: "r"(saddr), "l"(gaddr));
}
#define CP_COMMIT() asm volatile("cp.async.commit_group;" ::: "memory")
#define CP_WAIT(n)  asm volatile("cp.async.wait_group %0;" :: "n"(n) : "memory")

#define LDSM_X4(r, addr) \
    asm volatile("ldmatrix.sync.aligned.m8n8.x4.shared.b16 {%0,%1,%2,%3}, [%4];" \
        : "=r"((r)[0]), "=r"((r)[1]), "=r"((r)[2]), "=r"((r)[3]) : "r"(addr))

#define LDSM_X4_T(r, addr) \
    asm volatile("ldmatrix.sync.aligned.m8n8.x4.trans.shared.b16 {%0,%1,%2,%3}, [%4];" \
        : "=r"((r)[0]), "=r"((r)[1]), "=r"((r)[2]), "=r"((r)[3]) : "r"(addr))

__device__ __forceinline__ void mma16816(float* c, const uint32_t* a,
                                         uint32_t b0, uint32_t b1)
{
    asm volatile(
        "mma.sync.aligned.m16n8k16.row.col.f32.f16.f16.f32 "
        "{%0,%1,%2,%3}, {%4,%5,%6,%7}, {%8,%9}, {%0,%1,%2,%3};"
        : "+f"(c[0]), "+f"(c[1]), "+f"(c[2]), "+f"(c[3])
        : "r"(a[0]), "r"(a[1]), "r"(a[2]), "r"(a[3]), "r"(b0), "r"(b1));
}

__device__ __forceinline__ void split2(float v, fp16& hi, fp16& lo)
{
    hi = __float2half_rn(v);
    lo = __float2half_rn(v - __half2float(hi));
}

__device__ __forceinline__ uint32_t pack_h2(float a, float b)
{
    __half2 h = __floats2half2_rn(a, b);
    return *reinterpret_cast<uint32_t*>(&h);
}

__device__ __forceinline__ float gelu_f(float v)
{
    float c = 0.7978845608028654f * (v + 0.044715f * v * v * v);
    return 0.5f * v * (1.0f + tanhf(c));
}

// ---------------- weight transpose + split:  W[K][N] -> Wt_hi/lo[N][K] --------
__global__ void wconv_kernel(const float* __restrict__ W, fp16* __restrict__ hi,
                             fp16* __restrict__ lo, int K, int N)
{
    __shared__ float t[32][33];
    int n0 = blockIdx.x * 32, k0 = blockIdx.y * 32;
    int tx = threadIdx.x, ty = threadIdx.y;   // 32 x 8
    #pragma unroll
    for (int i = 0; i < 4; i++)
        t[ty + i * 8][tx] = W[(size_t)(k0 + ty + i * 8) * N + n0 + tx];
    __syncthreads();
    #pragma unroll
    for (int i = 0; i < 4; i++) {
        float v = t[tx][ty + i * 8];
        size_t o = (size_t)(n0 + ty + i * 8) * K + k0 + tx;
        fp16 h, l; split2(v, h, l);
        hi[o] = h; lo[o] = l;
    }
}

// ---------------- layernorm -> fp16 (hi only) ----------------------------------
__global__ void ln_kernel(const float* __restrict__ x, const float* __restrict__ w,
                          const float* __restrict__ b, fp16* __restrict__ hi)
{
    int row = blockIdx.x;
    int tid = threadIdx.x;
    const float4* xr = reinterpret_cast<const float4*>(x + (size_t)row * DD);
    float4 v = xr[tid];
    float s  = v.x + v.y + v.z + v.w;
    float ss = v.x*v.x + v.y*v.y + v.z*v.z + v.w*v.w;

    __shared__ float red0[8], red1[8], stat[2];
    #pragma unroll
    for (int o = 16; o; o >>= 1) {
        s  += __shfl_xor_sync(0xffffffffu, s,  o);
        ss += __shfl_xor_sync(0xffffffffu, ss, o);
    }
    int wid = tid >> 5, lane = tid & 31;
    if (lane == 0) { red0[wid] = s; red1[wid] = ss; }
    __syncthreads();
    if (tid == 0) {
        float ts = 0.f, tss = 0.f;
        #pragma unroll
        for (int i = 0; i < 8; i++) { ts += red0[i]; tss += red1[i]; }
        float mean = ts * (1.0f / DD);
        float var  = tss * (1.0f / DD) - mean * mean;
        stat[0] = mean;
        stat[1] = rsqrtf(var + 1e-5f);
    }
    __syncthreads();
    float mean = stat[0], rstd = stat[1];

    float4 wv = reinterpret_cast<const float4*>(w)[tid];
    float4 bv = reinterpret_cast<const float4*>(b)[tid];
    float o0 = wv.x * (v.x - mean) * rstd + bv.x;
    float o1 = wv.y * (v.y - mean) * rstd + bv.y;
    float o2 = wv.z * (v.z - mean) * rstd + bv.z;
    float o3 = wv.w * (v.w - mean) * rstd + bv.w;
    uint32_t* H = reinterpret_cast<uint32_t*>(hi + (size_t)row * DD);
    H[tid*2]   = pack_h2(o0, o1);
    H[tid*2+1] = pack_h2(o2, o3);
}

// ---------------- HMMA fp16x2 GEMM (3-stage) ------------------------------------
// C[M,N] = A[M,K] @ Bt[N,K]^T; A given hi-only, Bt hi/lo. BM=BN=128, BK=64.
// 256 threads = 8 warps, warp tile 32(m) x 64(n). 3 smem stages.
// EPI: 0 = bias->f32 ; 1 = bias+res->f32 ; 2 = gelu(bias)->fp16 hi
//      3 = bias (Q cols scaled 0.125) -> fp16 hi, lo only for K/V cols
#define SM_AHI 0
#define SM_BHI 16384
#define SM_BLO 32768
#define STAGE_BYTES 49152
#define TG_SMEM (3*STAGE_BYTES)

template<int K, int EPI>
__global__ __launch_bounds__(256, 1) void tgemm_kernel(
    const fp16* __restrict__ Ahi,
    const fp16* __restrict__ Bhi, const fp16* __restrict__ Blo,
    const float* __restrict__ bias, const float* __restrict__ res,
    float* __restrict__ Cf, fp16* __restrict__ Chi, fp16* __restrict__ Clo,
    int N)
{
    extern __shared__ char smem[];
    const uint32_t smem_base = smem_u32(smem);
    const int tid  = threadIdx.x;
    const int wid  = tid >> 5;
    const int lane = tid & 31;
    const int bx = blockIdx.x, by = blockIdx.y;
    const int wm = wid & 3;
    const int wn = wid >> 2;

    const fp16* Ah = Ahi + (size_t)by * 128 * K;
    const fp16* Bh = Bhi + (size_t)bx * 128 * K;
    const fp16* Bl = Blo + (size_t)bx * 128 * K;

    const int srow = tid >> 3;
    const int schk = tid & 7;

    auto stage = [&](int buf, int k0) {
        uint32_t sb = smem_base + buf * STAGE_BYTES;
        #pragma unroll
        for (int i = 0; i < 4; i++) {
            int row = srow + i * 32;
            size_t go = (size_t)row * K + k0 + schk * 8;
            uint32_t so = sw128((uint32_t)(row * 128 + schk * 16));
            cp16(sb + SM_AHI + so, Ah + go);
            cp16(sb + SM_BHI + so, Bh + go);
            cp16(sb + SM_BLO + so, Bl + go);
        }
        CP_COMMIT();
    };

    const int a_row = (lane & 15);
    const int a_col = (lane >> 4) * 16;
    const int b_row = (lane & 7) | ((lane >> 4) << 3);
    const int b_col = ((lane >> 3) & 1) * 16;

    float acc[2][8][4];
    #pragma unroll
    for (int mt = 0; mt < 2; mt++)
        #pragma unroll
        for (int nt = 0; nt < 8; nt++)
            #pragma unroll
            for (int i = 0; i < 4; i++) acc[mt][nt][i] = 0.f;

    constexpr int NC = K >> 6;
    stage(0, 0);
    stage(1, 64);

    #pragma unroll 1
    for (int c = 0; c < NC; c++) {
        if (c < NC - 1) { CP_WAIT(1); } else { CP_WAIT(0); }
        __syncthreads();
        if (c + 2 < NC) stage((c + 2) % 3, (c + 2) * 64);

        uint32_t sb = smem_base + (c % 3) * STAGE_BYTES;

        #pragma unroll
        for (int ks = 0; ks < 4; ks++) {
            int kb = ks * 32;

            uint32_t ah[2][4];
            #pragma unroll
            for (int mt = 0; mt < 2; mt++) {
                int row = wm * 32 + mt * 16 + a_row;
                uint32_t off = sw128((uint32_t)(row * 128 + kb + a_col));
                LDSM_X4(ah[mt], sb + SM_AHI + off);
            }
            uint32_t bh[4][4], bl[4][4];
            #pragma unroll
            for (int p = 0; p < 4; p++) {
                int row = wn * 64 + p * 16 + b_row;
                uint32_t off = sw128((uint32_t)(row * 128 + kb + b_col));
                LDSM_X4(bh[p], sb + SM_BHI + off);
                LDSM_X4(bl[p], sb + SM_BLO + off);
            }

            // term Ah*Bh: 16 independent MMAs
            #pragma unroll
            for (int mt = 0; mt < 2; mt++)
                #pragma unroll
                for (int p = 0; p < 4; p++) {
                    mma16816(acc[mt][2*p],   ah[mt], bh[p][0], bh[p][1]);
                    mma16816(acc[mt][2*p+1], ah[mt], bh[p][2], bh[p][3]);
                }
            // term Ah*Bl
            #pragma unroll
            for (int mt = 0; mt < 2; mt++)
                #pragma unroll
                for (int p = 0; p < 4; p++) {
                    mma16816(acc[mt][2*p],   ah[mt], bl[p][0], bl[p][1]);
                    mma16816(acc[mt][2*p+1], ah[mt], bl[p][2], bl[p][3]);
                }
        }
    }

    // ---- epilogue ----
    const int lrow = lane >> 2;
    const int lcol = (lane & 3) * 2;

    #pragma unroll
    for (int mt = 0; mt < 2; mt++) {
        #pragma unroll
        for (int nt = 0; nt < 8; nt++) {
            int Rg = by * 128 + wm * 32 + mt * 16 + lrow;
            int Cg = bx * 128 + wn * 64 + nt * 8 + lcol;
            float b0 = bias[Cg], b1 = bias[Cg + 1];
            #pragma unroll
            for (int h = 0; h < 2; h++) {
                int R = Rg + h * 8;
                float v0 = acc[mt][nt][h * 2 + 0] + b0;
                float v1 = acc[mt][nt][h * 2 + 1] + b1;
                if (EPI == 1) {
                    float2 rv = *reinterpret_cast<const float2*>(res + (size_t)R * N + Cg);
                    v0 += rv.x; v1 += rv.y;
                }
                if (EPI == 2) {
                    v0 = gelu_f(v0); v1 = gelu_f(v1);
                    *reinterpret_cast<uint32_t*>(Chi + (size_t)R * N + Cg) = pack_h2(v0, v1);
                } else if (EPI == 3) {
                    if (Cg < DD) {
                        // Q region: pre-scale, hi only
                        *reinterpret_cast<uint32_t*>(Chi + (size_t)R * N + Cg) =
                            pack_h2(v0 * 0.125f, v1 * 0.125f);
                    } else {
                        fp16 h0, l0, h1, l1;
                        split2(v0, h0, l0); split2(v1, h1, l1);
                        __half2 ph; ph.x = h0; ph.y = h1;
                        __half2 pl; pl.x = l0; pl.y = l1;
                        *reinterpret_cast<__half2*>(Chi + (size_t)R * N + Cg) = ph;
                        *reinterpret_cast<__half2*>(Clo + (size_t)R * N + Cg) = pl;
                    }
                } else {
                    float2 o; o.x = v0; o.y = v1;
                    *reinterpret_cast<float2*>(Cf + (size_t)R * N + Cg) = o;
                }
            }
        }
    }
}

// ---------------- tensor-core flash attention (causal, fp16x2) ------------------
// grid (S/128, B*H), 256 threads = 8 warps; warp w owns q rows w*16..w*16+15.
// smem: Q hi 128x64, 3-stage K/V hi/lo 64x64 tiles (SW128).
#define AQ_HI 0
#define ABUF  16384        // per buffer: KHI+0, KLO+8192, VHI+16384, VLO+24576
#define ABUF_SZ 32768
#define ATT_SMEM (ABUF + 3*ABUF_SZ)   // 114688

__global__ __launch_bounds__(256, 1) void attn_kernel(
    const fp16* __restrict__ qkv_hi, const fp16* __restrict__ qkv_lo,
    fp16* __restrict__ out_hi)
{
    extern __shared__ char smem[];
    const uint32_t sb = smem_u32(smem);
    const int qt  = blockIdx.x;
    const int bh  = blockIdx.y;
    const int bb  = bh >> 4;
    const int hh  = bh & 15;
    const int tid = threadIdx.x;
    const int w   = tid >> 5;
    const int lane = tid & 31;

    const size_t rowbase = (size_t)bb * SS;
    const int colq = hh * HD;

    // ---- stage Q (128 rows x 64 cols, hi); committed with KV tile 0 ----
    #pragma unroll
    for (int t = 0; t < 4; t++) {
        int idx = tid + t * 256;
        int row = idx >> 3, chk = idx & 7;
        size_t g = (rowbase + qt * 128 + row) * D3 + colq + chk * 8;
        uint32_t so = sw128((uint32_t)(row * 128 + chk * 16));
        cp16(sb + AQ_HI + so, qkv_hi + g);
    }

    auto stage_kv = [&](int buf, int kt) {
        uint32_t base = sb + ABUF + buf * ABUF_SZ;
        #pragma unroll
        for (int t = 0; t < 2; t++) {
            int idx = tid + t * 256;
            int row = idx >> 3, chk = idx & 7;
            size_t g = (rowbase + kt * 64 + row) * D3 + DD + colq + chk * 8;
            uint32_t so = sw128((uint32_t)(row * 128 + chk * 16));
            cp16(base + 0     + so, qkv_hi + g);
            cp16(base + 8192  + so, qkv_lo + g);
            cp16(base + 16384 + so, qkv_hi + g + DD);
            cp16(base + 24576 + so, qkv_lo + g + DD);
        }
        CP_COMMIT();
    };

    const int ktmax = 2 * qt + 1;
    stage_kv(0, 0);
    stage_kv(1, 1);   // ktmax >= 1 always

    // fragment addressing
    const int a_row = lane & 15;
    const int a_col = (lane >> 4) * 16;
    const int b_row = (lane & 7) | ((lane >> 4) << 3);
    const int b_col = ((lane >> 3) & 1) * 16;
    const int vt_row = ((lane >> 3) & 1) * 8 + (lane & 7);
    const int vt_col = ((lane >> 4) & 1) * 16;
    const int r0 = lane >> 2;
    const int c2 = (lane & 3) * 2;

    float oacc[8][4];
    #pragma unroll
    for (int nt = 0; nt < 8; nt++)
        #pragma unroll
        for (int i = 0; i < 4; i++) oacc[nt][i] = 0.f;
    float mrun[2] = {-1e30f, -1e30f}, lrun[2] = {0.f, 0.f};

    #pragma unroll 1
    for (int kt = 0; kt <= ktmax; kt++) {
        if (kt < ktmax) { CP_WAIT(1); } else { CP_WAIT(0); }
        __syncthreads();
        if (kt + 2 <= ktmax) stage_kv((kt + 2) % 3, kt + 2);

        uint32_t kvb = sb + ABUF + (kt % 3) * ABUF_SZ;

        // ---- S = Qh @ (Kh + Kl)^T ----
        float sacc[8][4];
        #pragma unroll
        for (int nt = 0; nt < 8; nt++)
            #pragma unroll
            for (int i = 0; i < 4; i++) sacc[nt][i] = 0.f;

        #pragma unroll
        for (int ks = 0; ks < 4; ks++) {
            int kb = ks * 32;
            uint32_t qh[4];
            {
                int row = w * 16 + a_row;
                uint32_t off = sw128((uint32_t)(row * 128 + kb + a_col));
                LDSM_X4(qh, sb + AQ_HI + off);
            }
            uint32_t kh[4][4], kl[4][4];
            #pragma unroll
            for (int g = 0; g < 4; g++) {
                int row = g * 16 + b_row;
                uint32_t off = sw128((uint32_t)(row * 128 + kb + b_col));
                LDSM_X4(kh[g], kvb + 0    + off);
                LDSM_X4(kl[g], kvb + 8192 + off);
            }
            #pragma unroll
            for (int g = 0; g < 4; g++) {
                mma16816(sacc[2*g],   qh, kh[g][0], kh[g][1]);
                mma16816(sacc[2*g+1], qh, kh[g][2], kh[g][3]);
            }
            #pragma unroll
            for (int g = 0; g < 4; g++) {
                mma16816(sacc[2*g],   qh, kl[g][0], kl[g][1]);
                mma16816(sacc[2*g+1], qh, kl[g][2], kl[g][3]);
            }
        }

        // ---- causal mask ----
        if (kt >= 2 * qt) {
            #pragma unroll
            for (int nt = 0; nt < 8; nt++)
                #pragma unroll
                for (int i = 0; i < 4; i++) {
                    int rg = qt * 128 + w * 16 + r0 + (i >> 1) * 8;
                    int cg = kt * 64 + nt * 8 + c2 + (i & 1);
                    if (cg > rg) sacc[nt][i] = -1e30f;
                }
        }

        // ---- online softmax (rows r0 and r0+8 per thread) ----
        float corr[2];
        #pragma unroll
        for (int h = 0; h < 2; h++) {
            float mx = -1e30f;
            #pragma unroll
            for (int nt = 0; nt < 8; nt++) {
                mx = fmaxf(mx, sacc[nt][h*2]);
                mx = fmaxf(mx, sacc[nt][h*2+1]);
            }
            mx = fmaxf(mx, __shfl_xor_sync(0xffffffffu, mx, 1));
            mx = fmaxf(mx, __shfl_xor_sync(0xffffffffu, mx, 2));
            float newm = fmaxf(mrun[h], mx);
            corr[h] = __expf(mrun[h] - newm);
            float ps = 0.f;
            #pragma unroll
            for (int nt = 0; nt < 8; nt++) {
                float p0 = __expf(sacc[nt][h*2]   - newm);
                float p1 = __expf(sacc[nt][h*2+1] - newm);
                sacc[nt][h*2] = p0; sacc[nt][h*2+1] = p1;
                ps += p0 + p1;
            }
            ps += __shfl_xor_sync(0xffffffffu, ps, 1);
            ps += __shfl_xor_sync(0xffffffffu, ps, 2);
            lrun[h] = lrun[h] * corr[h] + ps;
            mrun[h] = newm;
        }
        #pragma unroll
        for (int nt = 0; nt < 8; nt++) {
            oacc[nt][0] *= corr[0]; oacc[nt][1] *= corr[0];
            oacc[nt][2] *= corr[1]; oacc[nt][3] *= corr[1];
        }

        // ---- pack P (C-frag -> A-frag), fp16 single-term ----
        uint32_t pah[4][4];
        #pragma unroll
        for (int g = 0; g < 4; g++) {
            pah[g][0] = pack_h2(sacc[2*g][0],   sacc[2*g][1]);
            pah[g][1] = pack_h2(sacc[2*g][2],   sacc[2*g][3]);
            pah[g][2] = pack_h2(sacc[2*g+1][0], sacc[2*g+1][1]);
            pah[g][3] = pack_h2(sacc[2*g+1][2], sacc[2*g+1][3]);
        }

        // ---- O += Ph @ (Vh + Vl) (V via ldmatrix.trans) ----
        #pragma unroll
        for (int ks = 0; ks < 4; ks++) {
            uint32_t vh[4][4], vl[4][4];
            #pragma unroll
            for (int gd = 0; gd < 4; gd++) {
                int row = ks * 16 + vt_row;
                uint32_t off = sw128((uint32_t)(row * 128 + gd * 32 + vt_col));
                LDSM_X4_T(vh[gd], kvb + 16384 + off);
                LDSM_X4_T(vl[gd], kvb + 24576 + off);
            }
            #pragma unroll
            for (int gd = 0; gd < 4; gd++) {
                mma16816(oacc[2*gd],   pah[ks], vh[gd][0], vh[gd][1]);
                mma16816(oacc[2*gd+1], pah[ks], vh[gd][2], vh[gd][3]);
            }
            #pragma unroll
            for (int gd = 0; gd < 4; gd++) {
                mma16816(oacc[2*gd],   pah[ks], vl[gd][0], vl[gd][1]);
                mma16816(oacc[2*gd+1], pah[ks], vl[gd][2], vl[gd][3]);
            }
        }
    }

    // ---- epilogue (hi only) ----
    float inv[2] = {1.0f / lrun[0], 1.0f / lrun[1]};
    #pragma unroll
    for (int nt = 0; nt < 8; nt++) {
        #pragma unroll
        for (int h = 0; h < 2; h++) {
            int rg = qt * 128 + w * 16 + r0 + h * 8;
            int cg = colq + nt * 8 + c2;
            float v0 = oacc[nt][h*2]   * inv[h];
            float v1 = oacc[nt][h*2+1] * inv[h];
            size_t o = (rowbase + rg) * DD + cg;
            *reinterpret_cast<uint32_t*>(out_hi + o) = pack_h2(v0, v1);
        }
    }
}

// ---------------- launcher -----------------------------------------------------
extern "C" void kernel_launch(void* const* d_in, const int* in_sizes, int n_in,
                              void* d_out, int out_size)
{
    const float* x       = (const float*)d_in[0];
    const float* ln1_w   = (const float*)d_in[1];
    const float* ln1_b   = (const float*)d_in[2];
    const float* W_attn  = (const float*)d_in[3];
    const float* b_attn  = (const float*)d_in[4];
    const float* W_cproj = (const float*)d_in[5];
    const float* b_cproj = (const float*)d_in[6];
    const float* ln2_w   = (const float*)d_in[7];
    const float* ln2_b   = (const float*)d_in[8];
    const float* W_fc    = (const float*)d_in[9];
    const float* b_fc    = (const float*)d_in[10];
    const float* W_mproj = (const float*)d_in[11];
    const float* b_mproj = (const float*)d_in[12];
    float* out = (float*)d_out;

    float *x2;
    fp16 *qkv_hi, *qkv_lo, *h, *att, *m, *fc, *wt_hi, *wt_lo;
    cudaGetSymbolAddress((void**)&x2,     g_x2);
    cudaGetSymbolAddress((void**)&qkv_hi, g_qkv_hi);
    cudaGetSymbolAddress((void**)&qkv_lo, g_qkv_lo);
    cudaGetSymbolAddress((void**)&h,      g_h);
    cudaGetSymbolAddress((void**)&att,    g_att);
    cudaGetSymbolAddress((void**)&m,      g_m);
    cudaGetSymbolAddress((void**)&fc,     g_fc);
    cudaGetSymbolAddress((void**)&wt_hi,  g_wt_hi);
    cudaGetSymbolAddress((void**)&wt_lo,  g_wt_lo);

    cudaFuncSetAttribute(attn_kernel, cudaFuncAttributeMaxDynamicSharedMemorySize, ATT_SMEM);
    cudaFuncSetAttribute(tgemm_kernel<DD,3>, cudaFuncAttributeMaxDynamicSharedMemorySize, TG_SMEM);
    cudaFuncSetAttribute(tgemm_kernel<DD,1>, cudaFuncAttributeMaxDynamicSharedMemorySize, TG_SMEM);
    cudaFuncSetAttribute(tgemm_kernel<DD,2>, cudaFuncAttributeMaxDynamicSharedMemorySize, TG_SMEM);
    cudaFuncSetAttribute(tgemm_kernel<D4,1>, cudaFuncAttributeMaxDynamicSharedMemorySize, TG_SMEM);

    dim3 wblk(32, 8);
    wconv_kernel<<<dim3(D3 / 32, DD / 32), wblk>>>(W_attn,  wt_hi + WATTN_OFF,  wt_lo + WATTN_OFF,  DD, D3);
    wconv_kernel<<<dim3(DD / 32, DD / 32), wblk>>>(W_cproj, wt_hi + WCPROJ_OFF, wt_lo + WCPROJ_OFF, DD, DD);
    wconv_kernel<<<dim3(D4 / 32, DD / 32), wblk>>>(W_fc,    wt_hi + WFC_OFF,    wt_lo + WFC_OFF,    DD, D4);
    wconv_kernel<<<dim3(DD / 32, D4 / 32), wblk>>>(W_mproj, wt_hi + WMPROJ_OFF, wt_lo + WMPROJ_OFF, D4, DD);

    // 1. LN1 -> h
    ln_kernel<<<NTOK, 256>>>(x, ln1_w, ln1_b, h);

    // 2. qkv = h @ W_attn + b_attn  -> fp16 (Q pre-scaled hi-only; K/V hi+lo)
    tgemm_kernel<DD,3><<<dim3(D3 / 128, NTOK / 128), 256, TG_SMEM>>>(
        h, wt_hi + WATTN_OFF, wt_lo + WATTN_OFF,
        b_attn, nullptr, nullptr, qkv_hi, qkv_lo, D3);

    // 3. attention -> att
    attn_kernel<<<dim3(SS / 128, BB * HH), 256, ATT_SMEM>>>(qkv_hi, qkv_lo, att);

    // 4. x2 = att @ W_cproj + b_cproj + x
    tgemm_kernel<DD,1><<<dim3(DD / 128, NTOK / 128), 256, TG_SMEM>>>(
        att, wt_hi + WCPROJ_OFF, wt_lo + WCPROJ_OFF,
        b_cproj, x, x2, nullptr, nullptr, DD);

    // 5. LN2 -> m
    ln_kernel<<<NTOK, 256>>>(x2, ln2_w, ln2_b, m);

    // 6. fc = gelu(m @ W_fc + b_fc) -> fp16
    tgemm_kernel<DD,2><<<dim3(D4 / 128, NTOK / 128), 256, TG_SMEM>>>(
        m, wt_hi + WFC_OFF, wt_lo + WFC_OFF,
        b_fc, nullptr, nullptr, fc, nullptr, D4);

    // 7. out = fc @ W_mproj + b_mproj + x2
    tgemm_kernel<D4,1><<<dim3(DD / 128, NTOK / 128), 256, TG_SMEM>>>(
        fc, wt_hi + WMPROJ_OFF, wt_lo + WMPROJ_OFF,
        b_mproj, x2, out, nullptr, nullptr, DD);
}

// round 13
// speedup vs baseline: 8.9231x; 1.5419x over previous
#include <cuda_runtime.h>
#include <cuda_fp16.h>
#include <cstdint>
#include <cstddef>

typedef __half fp16;

// Problem constants
#define BB   4
#define SS   2048
#define DD   1024
#define HH   16
#define HD   64
#define NTOK (BB*SS)          // 8192
#define D3   (3*DD)           // 3072
#define D4   (4*DD)           // 4096

// ---------------- scratch (device globals) ------------------------------------
__device__ float g_x2 [NTOK*DD];
__device__ fp16  g_qkv[NTOK*D3];
__device__ fp16  g_h  [NTOK*DD];
__device__ fp16  g_att[NTOK*DD];
__device__ fp16  g_m  [NTOK*DD];
__device__ fp16  g_fc [NTOK*D4];

// transposed weights: Wt[N][K]
#define WATTN_OFF  0
#define WCPROJ_OFF (DD*D3)
#define WFC_OFF    (WCPROJ_OFF + DD*DD)
#define WMPROJ_OFF (WFC_OFF + DD*D4)
#define WTOTAL     (WMPROJ_OFF + D4*DD)
__device__ fp16 g_wt[WTOTAL];

// ---------------- helpers ------------------------------------------------------
__device__ __forceinline__ uint32_t smem_u32(const void* p) {
    uint32_t a;
    asm("{ .reg .u64 t; cvta.to.shared.u64 t, %1; cvt.u32.u64 %0, t; }" : "=r"(a) : "l"(p));
    return a;
}

__device__ __forceinline__ uint32_t sw128(uint32_t b) { return b ^ ((b >> 3) & 0x70); }

__device__ __forceinline__ void cp16(uint32_t saddr, const void* gaddr) {
    asm volatile("cp.async.cg.shared.global [%0], [%1], 16;" :: "r"(saddr), "l"(gaddr));
}
#define CP_COMMIT() asm volatile("cp.async.commit_group;" ::: "memory")
#define CP_WAIT(n)  asm volatile("cp.async.wait_group %0;" :: "n"(n) : "memory")

#define LDSM_X4(r, addr) \
    asm volatile("ldmatrix.sync.aligned.m8n8.x4.shared.b16 {%0,%1,%2,%3}, [%4];" \
        : "=r"((r)[0]), "=r"((r)[1]), "=r"((r)[2]), "=r"((r)[3]) : "r"(addr))

#define LDSM_X4_T(r, addr) \
    asm volatile("ldmatrix.sync.aligned.m8n8.x4.trans.shared.b16 {%0,%1,%2,%3}, [%4];" \
        : "=r"((r)[0]), "=r"((r)[1]), "=r"((r)[2]), "=r"((r)[3]) : "r"(addr))

__device__ __forceinline__ void mma16816(float* c, const uint32_t* a,
                                         uint32_t b0, uint32_t b1)
{
    asm volatile(
        "mma.sync.aligned.m16n8k16.row.col.f32.f16.f16.f32 "
        "{%0,%1,%2,%3}, {%4,%5,%6,%7}, {%8,%9}, {%0,%1,%2,%3};"
        : "+f"(c[0]), "+f"(c[1]), "+f"(c[2]), "+f"(c[3])
        : "r"(a[0]), "r"(a[1]), "r"(a[2]), "r"(a[3]), "r"(b0), "r"(b1));
}

__device__ __forceinline__ uint32_t pack_h2(float a, float b)
{
    __half2 h = __floats2half2_rn(a, b);
    return *reinterpret_cast<uint32_t*>(&h);
}

__device__ __forceinline__ float gelu_f(float v)
{
    float c = 0.7978845608028654f * (v + 0.044715f * v * v * v);
    return 0.5f * v * (1.0f + tanhf(c));
}

// ---------------- weight transpose + cast:  W[K][N] -> Wt[N][K] -----------------
__global__ void wconv_kernel(const float* __restrict__ W, fp16* __restrict__ o,
                             int K, int N)
{
    __shared__ float t[32][33];
    int n0 = blockIdx.x * 32, k0 = blockIdx.y * 32;
    int tx = threadIdx.x, ty = threadIdx.y;   // 32 x 8
    #pragma unroll
    for (int i = 0; i < 4; i++)
        t[ty + i * 8][tx] = W[(size_t)(k0 + ty + i * 8) * N + n0 + tx];
    __syncthreads();
    #pragma unroll
    for (int i = 0; i < 4; i++) {
        float v = t[tx][ty + i * 8];
        o[(size_t)(n0 + ty + i * 8) * K + k0 + tx] = __float2half_rn(v);
    }
}

// ---------------- layernorm -> fp16 --------------------------------------------
__global__ void ln_kernel(const float* __restrict__ x, const float* __restrict__ w,
                          const float* __restrict__ b, fp16* __restrict__ hi)
{
    int row = blockIdx.x;
    int tid = threadIdx.x;
    const float4* xr = reinterpret_cast<const float4*>(x + (size_t)row * DD);
    float4 v = xr[tid];
    float s  = v.x + v.y + v.z + v.w;
    float ss = v.x*v.x + v.y*v.y + v.z*v.z + v.w*v.w;

    __shared__ float red0[8], red1[8], stat[2];
    #pragma unroll
    for (int o = 16; o; o >>= 1) {
        s  += __shfl_xor_sync(0xffffffffu, s,  o);
        ss += __shfl_xor_sync(0xffffffffu, ss, o);
    }
    int wid = tid >> 5, lane = tid & 31;
    if (lane == 0) { red0[wid] = s; red1[wid] = ss; }
    __syncthreads();
    if (tid == 0) {
        float ts = 0.f, tss = 0.f;
        #pragma unroll
        for (int i = 0; i < 8; i++) { ts += red0[i]; tss += red1[i]; }
        float mean = ts * (1.0f / DD);
        float var  = tss * (1.0f / DD) - mean * mean;
        stat[0] = mean;
        stat[1] = rsqrtf(var + 1e-5f);
    }
    __syncthreads();
    float mean = stat[0], rstd = stat[1];

    float4 wv = reinterpret_cast<const float4*>(w)[tid];
    float4 bv = reinterpret_cast<const float4*>(b)[tid];
    float o0 = wv.x * (v.x - mean) * rstd + bv.x;
    float o1 = wv.y * (v.y - mean) * rstd + bv.y;
    float o2 = wv.z * (v.z - mean) * rstd + bv.z;
    float o3 = wv.w * (v.w - mean) * rstd + bv.w;
    uint32_t* H = reinterpret_cast<uint32_t*>(hi + (size_t)row * DD);
    H[tid*2]   = pack_h2(o0, o1);
    H[tid*2+1] = pack_h2(o2, o3);
}

// ---------------- HMMA fp16 GEMM (4-stage) --------------------------------------
// C[M,N] = A[M,K] @ Bt[N,K]^T. BM=BN=128, BK=64.
// 256 threads = 8 warps, warp tile 32(m) x 64(n). 4 smem stages.
// EPI: 1 = bias+res->f32 ; 2 = gelu(bias)->fp16 ; 3 = bias, Q cols scaled -> fp16
#define SM_A 0
#define SM_B 16384
#define STAGE_BYTES 32768
#define TG_SMEM (4*STAGE_BYTES)

template<int K, int EPI>
__global__ __launch_bounds__(256, 1) void tgemm_kernel(
    const fp16* __restrict__ A, const fp16* __restrict__ B,
    const float* __restrict__ bias, const float* __restrict__ res,
    float* __restrict__ Cf, fp16* __restrict__ Ch, int N)
{
    extern __shared__ char smem[];
    const uint32_t smem_base = smem_u32(smem);
    const int tid  = threadIdx.x;
    const int wid  = tid >> 5;
    const int lane = tid & 31;
    const int bx = blockIdx.x, by = blockIdx.y;
    const int wm = wid & 3;
    const int wn = wid >> 2;

    const fp16* Ab = A + (size_t)by * 128 * K;
    const fp16* Bb = B + (size_t)bx * 128 * K;

    const int srow = tid >> 3;
    const int schk = tid & 7;

    auto stage = [&](int buf, int k0) {
        uint32_t sb = smem_base + buf * STAGE_BYTES;
        #pragma unroll
        for (int i = 0; i < 4; i++) {
            int row = srow + i * 32;
            size_t go = (size_t)row * K + k0 + schk * 8;
            uint32_t so = sw128((uint32_t)(row * 128 + schk * 16));
            cp16(sb + SM_A + so, Ab + go);
            cp16(sb + SM_B + so, Bb + go);
        }
        CP_COMMIT();
    };

    const int a_row = (lane & 15);
    const int a_col = (lane >> 4) * 16;
    const int b_row = (lane & 7) | ((lane >> 4) << 3);
    const int b_col = ((lane >> 3) & 1) * 16;

    float acc[2][8][4];
    #pragma unroll
    for (int mt = 0; mt < 2; mt++)
        #pragma unroll
        for (int nt = 0; nt < 8; nt++)
            #pragma unroll
            for (int i = 0; i < 4; i++) acc[mt][nt][i] = 0.f;

    constexpr int NC = K >> 6;
    stage(0, 0);
    stage(1, 64);
    stage(2, 128);

    #pragma unroll 1
    for (int c = 0; c < NC; c++) {
        if (c < NC - 1) { CP_WAIT(2); } else { CP_WAIT(0); }
        __syncthreads();
        if (c + 3 < NC) stage((c + 3) & 3, (c + 3) * 64);

        uint32_t sb = smem_base + (c & 3) * STAGE_BYTES;

        #pragma unroll
        for (int ks = 0; ks < 4; ks++) {
            int kb = ks * 32;

            uint32_t ah[2][4];
            #pragma unroll
            for (int mt = 0; mt < 2; mt++) {
                int row = wm * 32 + mt * 16 + a_row;
                uint32_t off = sw128((uint32_t)(row * 128 + kb + a_col));
                LDSM_X4(ah[mt], sb + SM_A + off);
            }
            uint32_t bh[4][4];
            #pragma unroll
            for (int p = 0; p < 4; p++) {
                int row = wn * 64 + p * 16 + b_row;
                uint32_t off = sw128((uint32_t)(row * 128 + kb + b_col));
                LDSM_X4(bh[p], sb + SM_B + off);
            }
            #pragma unroll
            for (int mt = 0; mt < 2; mt++)
                #pragma unroll
                for (int p = 0; p < 4; p++) {
                    mma16816(acc[mt][2*p],   ah[mt], bh[p][0], bh[p][1]);
                    mma16816(acc[mt][2*p+1], ah[mt], bh[p][2], bh[p][3]);
                }
        }
    }

    // ---- epilogue ----
    const int lrow = lane >> 2;
    const int lcol = (lane & 3) * 2;

    #pragma unroll
    for (int mt = 0; mt < 2; mt++) {
        #pragma unroll
        for (int nt = 0; nt < 8; nt++) {
            int Rg = by * 128 + wm * 32 + mt * 16 + lrow;
            int Cg = bx * 128 + wn * 64 + nt * 8 + lcol;
            float b0 = bias[Cg], b1 = bias[Cg + 1];
            #pragma unroll
            for (int h = 0; h < 2; h++) {
                int R = Rg + h * 8;
                float v0 = acc[mt][nt][h * 2 + 0] + b0;
                float v1 = acc[mt][nt][h * 2 + 1] + b1;
                if (EPI == 1) {
                    float2 rv = *reinterpret_cast<const float2*>(res + (size_t)R * N + Cg);
                    float2 o; o.x = v0 + rv.x; o.y = v1 + rv.y;
                    *reinterpret_cast<float2*>(Cf + (size_t)R * N + Cg) = o;
                } else if (EPI == 2) {
                    *reinterpret_cast<uint32_t*>(Ch + (size_t)R * N + Cg) =
                        pack_h2(gelu_f(v0), gelu_f(v1));
                } else { // EPI == 3
                    if (Cg < DD) { v0 *= 0.125f; v1 *= 0.125f; }
                    *reinterpret_cast<uint32_t*>(Ch + (size_t)R * N + Cg) = pack_h2(v0, v1);
                }
            }
        }
    }
}

// ---------------- tensor-core flash attention (causal, fp16) --------------------
// grid (S/128, B*H), 256 threads = 8 warps; warp w owns q rows w*16..w*16+15.
// smem: Q 128x64, 3-stage K/V 64x64 tiles (SW128).
#define AQ    0
#define ABUF  16384        // per buffer: K+0, V+8192
#define ABUF_SZ 16384
#define ATT_SMEM (ABUF + 3*ABUF_SZ)   // 65536

__global__ __launch_bounds__(256, 1) void attn_kernel(
    const fp16* __restrict__ qkv, fp16* __restrict__ out)
{
    extern __shared__ char smem[];
    const uint32_t sb = smem_u32(smem);
    const int qt  = blockIdx.x;
    const int bh  = blockIdx.y;
    const int bb  = bh >> 4;
    const int hh  = bh & 15;
    const int tid = threadIdx.x;
    const int w   = tid >> 5;
    const int lane = tid & 31;

    const size_t rowbase = (size_t)bb * SS;
    const int colq = hh * HD;

    // ---- stage Q (128 rows x 64 cols) ----
    #pragma unroll
    for (int t = 0; t < 4; t++) {
        int idx = tid + t * 256;
        int row = idx >> 3, chk = idx & 7;
        size_t g = (rowbase + qt * 128 + row) * D3 + colq + chk * 8;
        uint32_t so = sw128((uint32_t)(row * 128 + chk * 16));
        cp16(sb + AQ + so, qkv + g);
    }

    auto stage_kv = [&](int buf, int kt) {
        uint32_t base = sb + ABUF + buf * ABUF_SZ;
        #pragma unroll
        for (int t = 0; t < 2; t++) {
            int idx = tid + t * 256;
            int row = idx >> 3, chk = idx & 7;
            size_t g = (rowbase + kt * 64 + row) * D3 + DD + colq + chk * 8;
            uint32_t so = sw128((uint32_t)(row * 128 + chk * 16));
            cp16(base + 0    + so, qkv + g);
            cp16(base + 8192 + so, qkv + g + DD);
        }
        CP_COMMIT();
    };

    const int ktmax = 2 * qt + 1;
    stage_kv(0, 0);
    stage_kv(1, 1);

    const int a_row = lane & 15;
    const int a_col = (lane >> 4) * 16;
    const int b_row = (lane & 7) | ((lane >> 4) << 3);
    const int b_col = ((lane >> 3) & 1) * 16;
    const int vt_row = ((lane >> 3) & 1) * 8 + (lane & 7);
    const int vt_col = ((lane >> 4) & 1) * 16;
    const int r0 = lane >> 2;
    const int c2 = (lane & 3) * 2;

    float oacc[8][4];
    #pragma unroll
    for (int nt = 0; nt < 8; nt++)
        #pragma unroll
        for (int i = 0; i < 4; i++) oacc[nt][i] = 0.f;
    float mrun[2] = {-1e30f, -1e30f}, lrun[2] = {0.f, 0.f};

    #pragma unroll 1
    for (int kt = 0; kt <= ktmax; kt++) {
        if (kt < ktmax) { CP_WAIT(1); } else { CP_WAIT(0); }
        __syncthreads();
        if (kt + 2 <= ktmax) stage_kv((kt + 2) % 3, kt + 2);

        uint32_t kvb = sb + ABUF + (kt % 3) * ABUF_SZ;

        // ---- S = Q @ K^T ----
        float sacc[8][4];
        #pragma unroll
        for (int nt = 0; nt < 8; nt++)
            #pragma unroll
            for (int i = 0; i < 4; i++) sacc[nt][i] = 0.f;

        #pragma unroll
        for (int ks = 0; ks < 4; ks++) {
            int kb = ks * 32;
            uint32_t qh[4];
            {
                int row = w * 16 + a_row;
                uint32_t off = sw128((uint32_t)(row * 128 + kb + a_col));
                LDSM_X4(qh, sb + AQ + off);
            }
            uint32_t kh[4][4];
            #pragma unroll
            for (int g = 0; g < 4; g++) {
                int row = g * 16 + b_row;
                uint32_t off = sw128((uint32_t)(row * 128 + kb + b_col));
                LDSM_X4(kh[g], kvb + off);
            }
            #pragma unroll
            for (int g = 0; g < 4; g++) {
                mma16816(sacc[2*g],   qh, kh[g][0], kh[g][1]);
                mma16816(sacc[2*g+1], qh, kh[g][2], kh[g][3]);
            }
        }

        // ---- causal mask ----
        if (kt >= 2 * qt) {
            #pragma unroll
            for (int nt = 0; nt < 8; nt++)
                #pragma unroll
                for (int i = 0; i < 4; i++) {
                    int rg = qt * 128 + w * 16 + r0 + (i >> 1) * 8;
                    int cg = kt * 64 + nt * 8 + c2 + (i & 1);
                    if (cg > rg) sacc[nt][i] = -1e30f;
                }
        }

        // ---- online softmax ----
        float corr[2];
        #pragma unroll
        for (int h = 0; h < 2; h++) {
            float mx = -1e30f;
            #pragma unroll
            for (int nt = 0; nt < 8; nt++) {
                mx = fmaxf(mx, sacc[nt][h*2]);
                mx = fmaxf(mx, sacc[nt][h*2+1]);
            }
            mx = fmaxf(mx, __shfl_xor_sync(0xffffffffu, mx, 1));
            mx = fmaxf(mx, __shfl_xor_sync(0xffffffffu, mx, 2));
            float newm = fmaxf(mrun[h], mx);
            corr[h] = __expf(mrun[h] - newm);
            float ps = 0.f;
            #pragma unroll
            for (int nt = 0; nt < 8; nt++) {
                float p0 = __expf(sacc[nt][h*2]   - newm);
                float p1 = __expf(sacc[nt][h*2+1] - newm);
                sacc[nt][h*2] = p0; sacc[nt][h*2+1] = p1;
                ps += p0 + p1;
            }
            ps += __shfl_xor_sync(0xffffffffu, ps, 1);
            ps += __shfl_xor_sync(0xffffffffu, ps, 2);
            lrun[h] = lrun[h] * corr[h] + ps;
            mrun[h] = newm;
        }
        #pragma unroll
        for (int nt = 0; nt < 8; nt++) {
            oacc[nt][0] *= corr[0]; oacc[nt][1] *= corr[0];
            oacc[nt][2] *= corr[1]; oacc[nt][3] *= corr[1];
        }

        // ---- pack P ----
        uint32_t pah[4][4];
        #pragma unroll
        for (int g = 0; g < 4; g++) {
            pah[g][0] = pack_h2(sacc[2*g][0],   sacc[2*g][1]);
            pah[g][1] = pack_h2(sacc[2*g][2],   sacc[2*g][3]);
            pah[g][2] = pack_h2(sacc[2*g+1][0], sacc[2*g+1][1]);
            pah[g][3] = pack_h2(sacc[2*g+1][2], sacc[2*g+1][3]);
        }

        // ---- O += P @ V ----
        #pragma unroll
        for (int ks = 0; ks < 4; ks++) {
            uint32_t vh[4][4];
            #pragma unroll
            for (int gd = 0; gd < 4; gd++) {
                int row = ks * 16 + vt_row;
                uint32_t off = sw128((uint32_t)(row * 128 + gd * 32 + vt_col));
                LDSM_X4_T(vh[gd], kvb + 8192 + off);
            }
            #pragma unroll
            for (int gd = 0; gd < 4; gd++) {
                mma16816(oacc[2*gd],   pah[ks], vh[gd][0], vh[gd][1]);
                mma16816(oacc[2*gd+1], pah[ks], vh[gd][2], vh[gd][3]);
            }
        }
    }

    // ---- epilogue ----
    float inv[2] = {1.0f / lrun[0], 1.0f / lrun[1]};
    #pragma unroll
    for (int nt = 0; nt < 8; nt++) {
        #pragma unroll
        for (int h = 0; h < 2; h++) {
            int rg = qt * 128 + w * 16 + r0 + h * 8;
            int cg = colq + nt * 8 + c2;
            float v0 = oacc[nt][h*2]   * inv[h];
            float v1 = oacc[nt][h*2+1] * inv[h];
            size_t o = (rowbase + rg) * DD + cg;
            *reinterpret_cast<uint32_t*>(out + o) = pack_h2(v0, v1);
        }
    }
}

// ---------------- launcher -----------------------------------------------------
extern "C" void kernel_launch(void* const* d_in, const int* in_sizes, int n_in,
                              void* d_out, int out_size)
{
    const float* x       = (const float*)d_in[0];
    const float* ln1_w   = (const float*)d_in[1];
    const float* ln1_b   = (const float*)d_in[2];
    const float* W_attn  = (const float*)d_in[3];
    const float* b_attn  = (const float*)d_in[4];
    const float* W_cproj = (const float*)d_in[5];
    const float* b_cproj = (const float*)d_in[6];
    const float* ln2_w   = (const float*)d_in[7];
    const float* ln2_b   = (const float*)d_in[8];
    const float* W_fc    = (const float*)d_in[9];
    const float* b_fc    = (const float*)d_in[10];
    const float* W_mproj = (const float*)d_in[11];
    const float* b_mproj = (const float*)d_in[12];
    float* out = (float*)d_out;

    float *x2;
    fp16 *qkv, *h, *att, *m, *fc, *wt;
    cudaGetSymbolAddress((void**)&x2,  g_x2);
    cudaGetSymbolAddress((void**)&qkv, g_qkv);
    cudaGetSymbolAddress((void**)&h,   g_h);
    cudaGetSymbolAddress((void**)&att, g_att);
    cudaGetSymbolAddress((void**)&m,   g_m);
    cudaGetSymbolAddress((void**)&fc,  g_fc);
    cudaGetSymbolAddress((void**)&wt,  g_wt);

    cudaFuncSetAttribute(attn_kernel, cudaFuncAttributeMaxDynamicSharedMemorySize, ATT_SMEM);
    cudaFuncSetAttribute(tgemm_kernel<DD,3>, cudaFuncAttributeMaxDynamicSharedMemorySize, TG_SMEM);
    cudaFuncSetAttribute(tgemm_kernel<DD,1>, cudaFuncAttributeMaxDynamicSharedMemorySize, TG_SMEM);
    cudaFuncSetAttribute(tgemm_kernel<DD,2>, cudaFuncAttributeMaxDynamicSharedMemorySize, TG_SMEM);
    cudaFuncSetAttribute(tgemm_kernel<D4,1>, cudaFuncAttributeMaxDynamicSharedMemorySize, TG_SMEM);

    dim3 wblk(32, 8);
    wconv_kernel<<<dim3(D3 / 32, DD / 32), wblk>>>(W_attn,  wt + WATTN_OFF,  DD, D3);
    wconv_kernel<<<dim3(DD / 32, DD / 32), wblk>>>(W_cproj, wt + WCPROJ_OFF, DD, DD);
    wconv_kernel<<<dim3(D4 / 32, DD / 32), wblk>>>(W_fc,    wt + WFC_OFF,    DD, D4);
    wconv_kernel<<<dim3(DD / 32, D4 / 32), wblk>>>(W_mproj, wt + WMPROJ_OFF, D4, DD);

    // 1. LN1 -> h
    ln_kernel<<<NTOK, 256>>>(x, ln1_w, ln1_b, h);

    // 2. qkv = h @ W_attn + b_attn -> fp16 (Q cols pre-scaled 1/8)
    tgemm_kernel<DD,3><<<dim3(D3 / 128, NTOK / 128), 256, TG_SMEM>>>(
        h, wt + WATTN_OFF, b_attn, nullptr, nullptr, qkv, D3);

    // 3. attention -> att
    attn_kernel<<<dim3(SS / 128, BB * HH), 256, ATT_SMEM>>>(qkv, att);

    // 4. x2 = att @ W_cproj + b_cproj + x
    tgemm_kernel<DD,1><<<dim3(DD / 128, NTOK / 128), 256, TG_SMEM>>>(
        att, wt + WCPROJ_OFF, b_cproj, x, x2, nullptr, DD);

    // 5. LN2 -> m
    ln_kernel<<<NTOK, 256>>>(x2, ln2_w, ln2_b, m);

    // 6. fc = gelu(m @ W_fc + b_fc) -> fp16
    tgemm_kernel<DD,2><<<dim3(D4 / 128, NTOK / 128), 256, TG_SMEM>>>(
        m, wt + WFC_OFF, b_fc, nullptr, nullptr, fc, D4);

    // 7. out = fc @ W_mproj + b_mproj + x2
    tgemm_kernel<D4,1><<<dim3(DD / 128, NTOK / 128), 256, TG_SMEM>>>(
        fc, wt + WMPROJ_OFF, b_mproj, x2, out, nullptr, DD);
}

// round 14
// speedup vs baseline: 10.4116x; 1.1668x over previous
#include <cuda_runtime.h>
#include <cuda_fp16.h>
#include <cstdint>
#include <cstddef>

typedef __half fp16;

// Problem constants
#define BB   4
#define SS   2048
#define DD   1024
#define HH   16
#define HD   64
#define NTOK (BB*SS)          // 8192
#define D3   (3*DD)           // 3072
#define D4   (4*DD)           // 4096

#define LOG2E 1.4426950408889634f

// ---------------- scratch (device globals) ------------------------------------
__device__ float g_x2 [NTOK*DD];
__device__ fp16  g_qkv[NTOK*D3];
__device__ fp16  g_h  [NTOK*DD];
__device__ fp16  g_att[NTOK*DD];
__device__ fp16  g_m  [NTOK*DD];
__device__ fp16  g_fc [NTOK*D4];

// transposed weights: Wt[N][K]
#define WATTN_OFF  0
#define WCPROJ_OFF (DD*D3)
#define WFC_OFF    (WCPROJ_OFF + DD*DD)
#define WMPROJ_OFF (WFC_OFF + DD*D4)
#define WTOTAL     (WMPROJ_OFF + D4*DD)
__device__ fp16 g_wt[WTOTAL];

// ---------------- helpers ------------------------------------------------------
__device__ __forceinline__ uint32_t smem_u32(const void* p) {
    uint32_t a;
    asm("{ .reg .u64 t; cvta.to.shared.u64 t, %1; cvt.u32.u64 %0, t; }" : "=r"(a) : "l"(p));
    return a;
}

__device__ __forceinline__ uint32_t sw128(uint32_t b) { return b ^ ((b >> 3) & 0x70); }

__device__ __forceinline__ void cp16(uint32_t saddr, const void* gaddr) {
    asm volatile("cp.async.cg.shared.global [%0], [%1], 16;" :: "r"(saddr), "l"(gaddr));
}
#define CP_COMMIT() asm volatile("cp.async.commit_group;" ::: "memory")
#define CP_WAIT(n)  asm volatile("cp.async.wait_group %0;" :: "n"(n) : "memory")

#define LDSM_X4(r, addr) \
    asm volatile("ldmatrix.sync.aligned.m8n8.x4.shared.b16 {%0,%1,%2,%3}, [%4];" \
        : "=r"((r)[0]), "=r"((r)[1]), "=r"((r)[2]), "=r"((r)[3]) : "r"(addr))

#define LDSM_X4_T(r, addr) \
    asm volatile("ldmatrix.sync.aligned.m8n8.x4.trans.shared.b16 {%0,%1,%2,%3}, [%4];" \
        : "=r"((r)[0]), "=r"((r)[1]), "=r"((r)[2]), "=r"((r)[3]) : "r"(addr))

__device__ __forceinline__ void mma16816(float* c, const uint32_t* a,
                                         uint32_t b0, uint32_t b1)
{
    asm volatile(
        "mma.sync.aligned.m16n8k16.row.col.f32.f16.f16.f32 "
        "{%0,%1,%2,%3}, {%4,%5,%6,%7}, {%8,%9}, {%0,%1,%2,%3};"
        : "+f"(c[0]), "+f"(c[1]), "+f"(c[2]), "+f"(c[3])
        : "r"(a[0]), "r"(a[1]), "r"(a[2]), "r"(a[3]), "r"(b0), "r"(b1));
}

__device__ __forceinline__ uint32_t pack_h2(float a, float b)
{
    __half2 h = __floats2half2_rn(a, b);
    return *reinterpret_cast<uint32_t*>(&h);
}

__device__ __forceinline__ float gelu_f(float v)
{
    float c = 0.7978845608028654f * (v + 0.044715f * v * v * v);
    return 0.5f * v * (1.0f + tanhf(c));
}

// ---------------- merged weight transpose + cast -------------------------------
__device__ __forceinline__ void wtile(const float* __restrict__ W, fp16* __restrict__ o,
                                      int K, int N, int n0, int k0)
{
    __shared__ float t[32][33];
    int tx = threadIdx.x, ty = threadIdx.y;   // 32 x 8
    #pragma unroll
    for (int i = 0; i < 4; i++)
        t[ty + i * 8][tx] = W[(size_t)(k0 + ty + i * 8) * N + n0 + tx];
    __syncthreads();
    #pragma unroll
    for (int i = 0; i < 4; i++) {
        float v = t[tx][ty + i * 8];
        o[(size_t)(n0 + ty + i * 8) * K + k0 + tx] = __float2half_rn(v);
    }
}

__global__ void wconv_all(const float* __restrict__ Wa, const float* __restrict__ Wc,
                          const float* __restrict__ Wf, const float* __restrict__ Wm,
                          fp16* __restrict__ wt)
{
    int b = blockIdx.x;
    if (b < 3072)       wtile(Wa, wt + WATTN_OFF,  DD, D3, (b % 96) * 32, (b / 96) * 32);
    else if (b < 4096)  { b -= 3072; wtile(Wc, wt + WCPROJ_OFF, DD, DD, (b % 32) * 32, (b / 32) * 32); }
    else if (b < 8192)  { b -= 4096; wtile(Wf, wt + WFC_OFF,    DD, D4, (b % 128) * 32, (b / 128) * 32); }
    else                { b -= 8192; wtile(Wm, wt + WMPROJ_OFF, D4, DD, (b % 32) * 32, (b / 32) * 32); }
}

// ---------------- layernorm -> fp16 --------------------------------------------
__global__ void ln_kernel(const float* __restrict__ x, const float* __restrict__ w,
                          const float* __restrict__ b, fp16* __restrict__ hi)
{
    int row = blockIdx.x;
    int tid = threadIdx.x;
    const float4* xr = reinterpret_cast<const float4*>(x + (size_t)row * DD);
    float4 v = xr[tid];
    float s  = v.x + v.y + v.z + v.w;
    float ss = v.x*v.x + v.y*v.y + v.z*v.z + v.w*v.w;

    __shared__ float red0[8], red1[8], stat[2];
    #pragma unroll
    for (int o = 16; o; o >>= 1) {
        s  += __shfl_xor_sync(0xffffffffu, s,  o);
        ss += __shfl_xor_sync(0xffffffffu, ss, o);
    }
    int wid = tid >> 5, lane = tid & 31;
    if (lane == 0) { red0[wid] = s; red1[wid] = ss; }
    __syncthreads();
    if (tid == 0) {
        float ts = 0.f, tss = 0.f;
        #pragma unroll
        for (int i = 0; i < 8; i++) { ts += red0[i]; tss += red1[i]; }
        float mean = ts * (1.0f / DD);
        float var  = tss * (1.0f / DD) - mean * mean;
        stat[0] = mean;
        stat[1] = rsqrtf(var + 1e-5f);
    }
    __syncthreads();
    float mean = stat[0], rstd = stat[1];

    float4 wv = reinterpret_cast<const float4*>(w)[tid];
    float4 bv = reinterpret_cast<const float4*>(b)[tid];
    float o0 = wv.x * (v.x - mean) * rstd + bv.x;
    float o1 = wv.y * (v.y - mean) * rstd + bv.y;
    float o2 = wv.z * (v.z - mean) * rstd + bv.z;
    float o3 = wv.w * (v.w - mean) * rstd + bv.w;
    uint32_t* H = reinterpret_cast<uint32_t*>(hi + (size_t)row * DD);
    H[tid*2]   = pack_h2(o0, o1);
    H[tid*2+1] = pack_h2(o2, o3);
}

// ---------------- HMMA fp16 GEMM (3-stage, templated BN) ------------------------
// C[M,N] = A[M,K] @ Bt[N,K]^T. BM=128, BN in {128,256}, BK=64.
// 256 threads = 8 warps; warp tile 32(m) x BN/2(n).
// EPI: 1 = bias+res->f32 ; 2 = gelu(bias)->fp16 ; 3 = bias, Q cols scaled -> fp16
#define SM_A 0
#define SM_B 16384

template<int K, int BN, int EPI>
__global__ __launch_bounds__(256, 1) void tgemm_kernel(
    const fp16* __restrict__ A, const fp16* __restrict__ B,
    const float* __restrict__ bias, const float* __restrict__ res,
    float* __restrict__ Cf, fp16* __restrict__ Ch, int N)
{
    constexpr int STAGE_BYTES = 16384 + BN * 128;
    constexpr int NT = BN / 16;       // mma n-tiles per warp
    constexpr int PG = BN / 32;       // 16-row B groups per warp

    extern __shared__ char smem[];
    const uint32_t smem_base = smem_u32(smem);
    const int tid  = threadIdx.x;
    const int wid  = tid >> 5;
    const int lane = tid & 31;
    const int bx = blockIdx.x, by = blockIdx.y;
    const int wm = wid & 3;
    const int wn = wid >> 2;

    const fp16* Ab = A + (size_t)by * 128 * K;
    const fp16* Bb = B + (size_t)bx * BN * K;

    const int srow = tid >> 3;
    const int schk = tid & 7;

    auto stage = [&](int buf, int k0) {
        uint32_t sb = smem_base + buf * STAGE_BYTES;
        #pragma unroll
        for (int i = 0; i < 4; i++) {
            int row = srow + i * 32;
            size_t go = (size_t)row * K + k0 + schk * 8;
            uint32_t so = sw128((uint32_t)(row * 128 + schk * 16));
            cp16(sb + SM_A + so, Ab + go);
        }
        #pragma unroll
        for (int i = 0; i < BN / 32; i++) {
            int row = srow + i * 32;
            size_t go = (size_t)row * K + k0 + schk * 8;
            uint32_t so = sw128((uint32_t)(row * 128 + schk * 16));
            cp16(sb + SM_B + so, Bb + go);
        }
        CP_COMMIT();
    };

    const int a_row = (lane & 15);
    const int a_col = (lane >> 4) * 16;
    const int b_row = (lane & 7) | ((lane >> 4) << 3);
    const int b_col = ((lane >> 3) & 1) * 16;

    float acc[2][NT][4];
    #pragma unroll
    for (int mt = 0; mt < 2; mt++)
        #pragma unroll
        for (int nt = 0; nt < NT; nt++)
            #pragma unroll
            for (int i = 0; i < 4; i++) acc[mt][nt][i] = 0.f;

    constexpr int NC = K >> 6;
    stage(0, 0);
    stage(1, 64);

    #pragma unroll 1
    for (int c = 0; c < NC; c++) {
        if (c < NC - 1) { CP_WAIT(1); } else { CP_WAIT(0); }
        __syncthreads();
        if (c + 2 < NC) stage((c + 2) % 3, (c + 2) * 64);

        uint32_t sb = smem_base + (c % 3) * STAGE_BYTES;

        #pragma unroll
        for (int ks = 0; ks < 4; ks++) {
            int kb = ks * 32;

            uint32_t ah[2][4];
            #pragma unroll
            for (int mt = 0; mt < 2; mt++) {
                int row = wm * 32 + mt * 16 + a_row;
                uint32_t off = sw128((uint32_t)(row * 128 + kb + a_col));
                LDSM_X4(ah[mt], sb + SM_A + off);
            }
            uint32_t bh[PG][4];
            #pragma unroll
            for (int p = 0; p < PG; p++) {
                int row = wn * (BN / 2) + p * 16 + b_row;
                uint32_t off = sw128((uint32_t)(row * 128 + kb + b_col));
                LDSM_X4(bh[p], sb + SM_B + off);
            }
            #pragma unroll
            for (int mt = 0; mt < 2; mt++)
                #pragma unroll
                for (int p = 0; p < PG; p++) {
                    mma16816(acc[mt][2*p],   ah[mt], bh[p][0], bh[p][1]);
                    mma16816(acc[mt][2*p+1], ah[mt], bh[p][2], bh[p][3]);
                }
        }
    }

    // ---- epilogue ----
    const int lrow = lane >> 2;
    const int lcol = (lane & 3) * 2;

    #pragma unroll
    for (int mt = 0; mt < 2; mt++) {
        #pragma unroll
        for (int nt = 0; nt < NT; nt++) {
            int Rg = by * 128 + wm * 32 + mt * 16 + lrow;
            int Cg = bx * BN + wn * (BN / 2) + nt * 8 + lcol;
            float b0 = bias[Cg], b1 = bias[Cg + 1];
            #pragma unroll
            for (int h = 0; h < 2; h++) {
                int R = Rg + h * 8;
                float v0 = acc[mt][nt][h * 2 + 0] + b0;
                float v1 = acc[mt][nt][h * 2 + 1] + b1;
                if (EPI == 1) {
                    float2 rv = *reinterpret_cast<const float2*>(res + (size_t)R * N + Cg);
                    float2 o; o.x = v0 + rv.x; o.y = v1 + rv.y;
                    *reinterpret_cast<float2*>(Cf + (size_t)R * N + Cg) = o;
                } else if (EPI == 2) {
                    *reinterpret_cast<uint32_t*>(Ch + (size_t)R * N + Cg) =
                        pack_h2(gelu_f(v0), gelu_f(v1));
                } else { // EPI == 3: Q cols pre-scaled by 0.125*log2e for exp2 softmax
                    if (Cg < DD) { v0 *= 0.125f * LOG2E; v1 *= 0.125f * LOG2E; }
                    *reinterpret_cast<uint32_t*>(Ch + (size_t)R * N + Cg) = pack_h2(v0, v1);
                }
            }
        }
    }
}

// ---------------- tensor-core flash attention (causal, fp16, 128-key tiles) -----
// grid (S/128, B*H), 256 threads = 8 warps; warp w owns q rows w*16..w*16+15.
// smem: Q 128x64, 3-stage K/V 128x64 tiles (SW128). Scores in log2 domain.
#define AQ      0
#define ABUF    16384       // per stage: K(16KB) + V(16KB)
#define ABUF_SZ 32768
#define ATT_SMEM (ABUF + 3*ABUF_SZ)   // 114688

__global__ __launch_bounds__(256, 1) void attn_kernel(
    const fp16* __restrict__ qkv, fp16* __restrict__ out)
{
    extern __shared__ char smem[];
    const uint32_t sb = smem_u32(smem);
    const int qt  = blockIdx.x;
    const int bh  = blockIdx.y;
    const int bb  = bh >> 4;
    const int hh  = bh & 15;
    const int tid = threadIdx.x;
    const int w   = tid >> 5;
    const int lane = tid & 31;

    const size_t rowbase = (size_t)bb * SS;
    const int colq = hh * HD;

    // ---- stage Q (128 rows x 64 cols) ----
    #pragma unroll
    for (int t = 0; t < 4; t++) {
        int idx = tid + t * 256;
        int row = idx >> 3, chk = idx & 7;
        size_t g = (rowbase + qt * 128 + row) * D3 + colq + chk * 8;
        uint32_t so = sw128((uint32_t)(row * 128 + chk * 16));
        cp16(sb + AQ + so, qkv + g);
    }

    auto stage_kv = [&](int buf, int kt) {
        uint32_t base = sb + ABUF + buf * ABUF_SZ;
        #pragma unroll
        for (int t = 0; t < 4; t++) {
            int idx = tid + t * 256;
            int row = idx >> 3, chk = idx & 7;
            size_t g = (rowbase + kt * 128 + row) * D3 + DD + colq + chk * 8;
            uint32_t so = sw128((uint32_t)(row * 128 + chk * 16));
            cp16(base + 0     + so, qkv + g);
            cp16(base + 16384 + so, qkv + g + DD);
        }
        CP_COMMIT();
    };

    const int ktmax = qt;
    stage_kv(0, 0);
    if (ktmax >= 1) stage_kv(1, 1);

    const int a_row = lane & 15;
    const int a_col = (lane >> 4) * 16;
    const int b_row = (lane & 7) | ((lane >> 4) << 3);
    const int b_col = ((lane >> 3) & 1) * 16;
    const int vt_row = ((lane >> 3) & 1) * 8 + (lane & 7);
    const int vt_col = ((lane >> 4) & 1) * 16;
    const int r0 = lane >> 2;
    const int c2 = (lane & 3) * 2;

    float oacc[8][4];
    #pragma unroll
    for (int nt = 0; nt < 8; nt++)
        #pragma unroll
        for (int i = 0; i < 4; i++) oacc[nt][i] = 0.f;
    float mrun[2] = {-1e30f, -1e30f}, lrun[2] = {0.f, 0.f};

    #pragma unroll 1
    for (int kt = 0; kt <= ktmax; kt++) {
        if (kt < ktmax) { CP_WAIT(1); } else { CP_WAIT(0); }
        __syncthreads();
        if (kt + 2 <= ktmax) stage_kv((kt + 2) % 3, kt + 2);

        uint32_t kvb = sb + ABUF + (kt % 3) * ABUF_SZ;

        // ---- S = Q @ K^T (128 keys, log2 domain) ----
        float sacc[16][4];
        #pragma unroll
        for (int nt = 0; nt < 16; nt++)
            #pragma unroll
            for (int i = 0; i < 4; i++) sacc[nt][i] = 0.f;

        #pragma unroll
        for (int ks = 0; ks < 4; ks++) {
            int kb = ks * 32;
            uint32_t qh[4];
            {
                int row = w * 16 + a_row;
                uint32_t off = sw128((uint32_t)(row * 128 + kb + a_col));
                LDSM_X4(qh, sb + AQ + off);
            }
            uint32_t kh[8][4];
            #pragma unroll
            for (int g = 0; g < 8; g++) {
                int row = g * 16 + b_row;
                uint32_t off = sw128((uint32_t)(row * 128 + kb + b_col));
                LDSM_X4(kh[g], kvb + off);
            }
            #pragma unroll
            for (int g = 0; g < 8; g++) {
                mma16816(sacc[2*g],   qh, kh[g][0], kh[g][1]);
                mma16816(sacc[2*g+1], qh, kh[g][2], kh[g][3]);
            }
        }

        // ---- causal mask (diagonal tile only) ----
        if (kt == qt) {
            #pragma unroll
            for (int nt = 0; nt < 16; nt++)
                #pragma unroll
                for (int i = 0; i < 4; i++) {
                    int rl = w * 16 + r0 + (i >> 1) * 8;
                    int cl = nt * 8 + c2 + (i & 1);
                    if (cl > rl) sacc[nt][i] = -1e30f;
                }
        }

        // ---- online softmax (base-2) ----
        float corr[2];
        #pragma unroll
        for (int h = 0; h < 2; h++) {
            float mx = -1e30f;
            #pragma unroll
            for (int nt = 0; nt < 16; nt++) {
                mx = fmaxf(mx, sacc[nt][h*2]);
                mx = fmaxf(mx, sacc[nt][h*2+1]);
            }
            mx = fmaxf(mx, __shfl_xor_sync(0xffffffffu, mx, 1));
            mx = fmaxf(mx, __shfl_xor_sync(0xffffffffu, mx, 2));
            float newm = fmaxf(mrun[h], mx);
            corr[h] = exp2f(mrun[h] - newm);
            float ps = 0.f;
            #pragma unroll
            for (int nt = 0; nt < 16; nt++) {
                float p0 = exp2f(sacc[nt][h*2]   - newm);
                float p1 = exp2f(sacc[nt][h*2+1] - newm);
                sacc[nt][h*2] = p0; sacc[nt][h*2+1] = p1;
                ps += p0 + p1;
            }
            ps += __shfl_xor_sync(0xffffffffu, ps, 1);
            ps += __shfl_xor_sync(0xffffffffu, ps, 2);
            lrun[h] = lrun[h] * corr[h] + ps;
            mrun[h] = newm;
        }
        #pragma unroll
        for (int nt = 0; nt < 8; nt++) {
            oacc[nt][0] *= corr[0]; oacc[nt][1] *= corr[0];
            oacc[nt][2] *= corr[1]; oacc[nt][3] *= corr[1];
        }

        // ---- pack P (16q x 128k -> 8 A-fragments) ----
        uint32_t pah[8][4];
        #pragma unroll
        for (int g = 0; g < 8; g++) {
            pah[g][0] = pack_h2(sacc[2*g][0],   sacc[2*g][1]);
            pah[g][1] = pack_h2(sacc[2*g][2],   sacc[2*g][3]);
            pah[g][2] = pack_h2(sacc[2*g+1][0], sacc[2*g+1][1]);
            pah[g][3] = pack_h2(sacc[2*g+1][2], sacc[2*g+1][3]);
        }

        // ---- O += P @ V (V via ldmatrix.trans; 8 ksteps over 128 keys) ----
        #pragma unroll
        for (int ks = 0; ks < 8; ks++) {
            uint32_t vh[4][4];
            #pragma unroll
            for (int gd = 0; gd < 4; gd++) {
                int row = ks * 16 + vt_row;
                uint32_t off = sw128((uint32_t)(row * 128 + gd * 32 + vt_col));
                LDSM_X4_T(vh[gd], kvb + 16384 + off);
            }
            #pragma unroll
            for (int gd = 0; gd < 4; gd++) {
                mma16816(oacc[2*gd],   pah[ks], vh[gd][0], vh[gd][1]);
                mma16816(oacc[2*gd+1], pah[ks], vh[gd][2], vh[gd][3]);
            }
        }
    }

    // ---- epilogue ----
    float inv[2] = {1.0f / lrun[0], 1.0f / lrun[1]};
    #pragma unroll
    for (int nt = 0; nt < 8; nt++) {
        #pragma unroll
        for (int h = 0; h < 2; h++) {
            int rg = qt * 128 + w * 16 + r0 + h * 8;
            int cg = colq + nt * 8 + c2;
            float v0 = oacc[nt][h*2]   * inv[h];
            float v1 = oacc[nt][h*2+1] * inv[h];
            size_t o = (rowbase + rg) * DD + cg;
            *reinterpret_cast<uint32_t*>(out + o) = pack_h2(v0, v1);
        }
    }
}

// ---------------- launcher -----------------------------------------------------
extern "C" void kernel_launch(void* const* d_in, const int* in_sizes, int n_in,
                              void* d_out, int out_size)
{
    const float* x       = (const float*)d_in[0];
    const float* ln1_w   = (const float*)d_in[1];
    const float* ln1_b   = (const float*)d_in[2];
    const float* W_attn  = (const float*)d_in[3];
    const float* b_attn  = (const float*)d_in[4];
    const float* W_cproj = (const float*)d_in[5];
    const float* b_cproj = (const float*)d_in[6];
    const float* ln2_w   = (const float*)d_in[7];
    const float* ln2_b   = (const float*)d_in[8];
    const float* W_fc    = (const float*)d_in[9];
    const float* b_fc    = (const float*)d_in[10];
    const float* W_mproj = (const float*)d_in[11];
    const float* b_mproj = (const float*)d_in[12];
    float* out = (float*)d_out;

    float *x2;
    fp16 *qkv, *h, *att, *m, *fc, *wt;
    cudaGetSymbolAddress((void**)&x2,  g_x2);
    cudaGetSymbolAddress((void**)&qkv, g_qkv);
    cudaGetSymbolAddress((void**)&h,   g_h);
    cudaGetSymbolAddress((void**)&att, g_att);
    cudaGetSymbolAddress((void**)&m,   g_m);
    cudaGetSymbolAddress((void**)&fc,  g_fc);
    cudaGetSymbolAddress((void**)&wt,  g_wt);

    constexpr int SM128 = 3 * (16384 + 128 * 128);  //  96 KB
    constexpr int SM256 = 3 * (16384 + 256 * 128);  // 144 KB

    cudaFuncSetAttribute(attn_kernel, cudaFuncAttributeMaxDynamicSharedMemorySize, ATT_SMEM);
    cudaFuncSetAttribute(tgemm_kernel<DD,256,3>, cudaFuncAttributeMaxDynamicSharedMemorySize, SM256);
    cudaFuncSetAttribute(tgemm_kernel<DD,128,1>, cudaFuncAttributeMaxDynamicSharedMemorySize, SM128);
    cudaFuncSetAttribute(tgemm_kernel<DD,256,2>, cudaFuncAttributeMaxDynamicSharedMemorySize, SM256);
    cudaFuncSetAttribute(tgemm_kernel<D4,256,1>, cudaFuncAttributeMaxDynamicSharedMemorySize, SM256);

    // weight transpose + cast (single merged launch)
    wconv_all<<<12288, dim3(32, 8)>>>(W_attn, W_cproj, W_fc, W_mproj, wt);

    // 1. LN1 -> h
    ln_kernel<<<NTOK, 256>>>(x, ln1_w, ln1_b, h);

    // 2. qkv = h @ W_attn + b_attn -> fp16 (Q cols pre-scaled 0.125*log2e)
    tgemm_kernel<DD,256,3><<<dim3(D3 / 256, NTOK / 128), 256, SM256>>>(
        h, wt + WATTN_OFF, b_attn, nullptr, nullptr, qkv, D3);

    // 3. attention -> att
    attn_kernel<<<dim3(SS / 128, BB * HH), 256, ATT_SMEM>>>(qkv, att);

    // 4. x2 = att @ W_cproj + b_cproj + x
    tgemm_kernel<DD,128,1><<<dim3(DD / 128, NTOK / 128), 256, SM128>>>(
        att, wt + WCPROJ_OFF, b_cproj, x, x2, nullptr, DD);

    // 5. LN2 -> m
    ln_kernel<<<NTOK, 256>>>(x2, ln2_w, ln2_b, m);

    // 6. fc = gelu(m @ W_fc + b_fc) -> fp16
    tgemm_kernel<DD,256,2><<<dim3(D4 / 256, NTOK / 128), 256, SM256>>>(
        m, wt + WFC_OFF, b_fc, nullptr, nullptr, fc, D4);

    // 7. out = fc @ W_mproj + b_mproj + x2
    tgemm_kernel<D4,256,1><<<dim3(DD / 256, NTOK / 128), 256, SM256>>>(
        fc, wt + WMPROJ_OFF, b_mproj, x2, out, nullptr, DD);
}